// round 2
// baseline (speedup 1.0000x reference)
#include <cuda_runtime.h>
#include <cstdint>

// Attention with exact JAX threefry dropout (PARTITIONABLE path), fp32
// flash-attention style. B=4, Q=4096, NKV=4096, H=128. scale = +sqrt(128).
//
// Grid: 128 CTAs = 4 batches x 32 q-tiles of 128 rows. 512 threads.
// Per KV tile (64 rows): S = Q K^T (4x4 microtile / thread), online softmax
// with register-resident per-row stats (replicated across the 16 threads of a
// row, shuffle-reduced), threefry dropout mask on P, then O += P V (4x8
// microtile / thread, same row ownership).

#define TB   512
#define BQ   128
#define BKV  64
#define HD   128
#define NKV  4096
#define NQ   4096

// smem pitches (floats) chosen for 16B-aligned LDS.128 + low bank conflicts
#define PQ   132
#define PK   68
#define PV   132
#define PP   68

#define SMEM_FLOATS (128*PQ + 128*PK + BKV*PV + BQ*PP)

// ---------------------------------------------------------------------------
// JAX threefry2x32-20, key = (0, 42), PARTITIONABLE layout (default since
// jax 0.4.30): element i uses 64-bit counter i split as (hi, lo) = (0, i):
//   x0 = 0 + ks0, x1 = i + ks1 ; 20 rounds ; bits = x0_out ^ x1_out
// uniform u = ((bits >> 9) | 0x3f800000) - 1.0 ; keep = u < 0.9f
//   <=> (bits >> 9) < 7549747   (0.9f == 7549747 * 2^-23 exactly)
// ---------------------------------------------------------------------------
__device__ __forceinline__ unsigned keep_mask(unsigned idx) {
  const unsigned ks1 = 42u;
  const unsigned ks2 = 0x1BD11BDAu ^ 42u;   // 0x1BD11BDA ^ ks0 ^ ks1, ks0 = 0
  unsigned x0 = 0u;                          // counts_hi + ks0
  unsigned x1 = idx + ks1;                   // counts_lo + ks1
#define TFR(r) { x0 += x1; x1 = __funnelshift_l(x1, x1, (r)); x1 ^= x0; }
  TFR(13) TFR(15) TFR(26) TFR(6)
  x0 += ks1; x1 += ks2 + 1u;
  TFR(17) TFR(29) TFR(16) TFR(24)
  x0 += ks2; x1 += 2u;                       // + ks0 + 2
  TFR(13) TFR(15) TFR(26) TFR(6)
  /* x0 += ks0 */ x1 += ks1 + 3u;
  TFR(17) TFR(29) TFR(16) TFR(24)
  x0 += ks1; x1 += ks2 + 4u;
  TFR(13) TFR(15) TFR(26) TFR(6)
  x0 += ks2; x1 += 5u;                       // + ks0 + 5
#undef TFR
  unsigned bits = x0 ^ x1;                   // partitionable 32-bit output
  return (bits >> 9) < 7549747u;
}

__global__ void __launch_bounds__(TB, 1)
Model_56358560858161_kernel(const float* __restrict__ Qg,
                            const float* __restrict__ Kg,
                            const float* __restrict__ Vg,
                            float* __restrict__ Og)
{
  extern __shared__ float smem[];
  float* Qt = smem;                 // [HD][PQ]  Q^T, pre-scaled by sqrt(128)
  float* Kt = Qt + 128 * PQ;        // [HD][PK]  K^T (tile)
  float* Vs = Kt + 128 * PK;        // [BKV][PV] V   (tile)
  float* Ps = Vs + BKV * PV;        // [BQ][PP]  masked probabilities

  const int tid = threadIdx.x;
  const int ty  = tid >> 4;         // 0..31  -> rows 4*ty..4*ty+3
  const int tx  = tid & 15;         // 0..15  -> S cols 4*tx.., AV cols 8*tx..
  const int b   = blockIdx.x >> 5;
  const int q0  = (blockIdx.x & 31) * BQ;

  const float* Qb = Qg + (size_t)b * NQ  * HD;
  const float* Kb = Kg + (size_t)b * NKV * HD;
  const float* Vb = Vg + (size_t)b * NKV * HD;

  const float SCALE = 11.3137084989847603904f;  // sqrt(128)

  // ---- load Q tile, transposed + pre-scaled --------------------------------
  #pragma unroll
  for (int it = 0; it < (BQ * HD) / TB; ++it) {
    int idx = tid + it * TB;
    int r = idx >> 7, h = idx & 127;
    Qt[h * PQ + r] = Qb[(q0 + r) * HD + h] * SCALE;
  }

  float m[4], l[4], sc[4], O[4][8];
  #pragma unroll
  for (int i = 0; i < 4; ++i) {
    m[i] = -1e30f; l[i] = 0.f;
    #pragma unroll
    for (int h = 0; h < 8; ++h) O[i][h] = 0.f;
  }

  const unsigned gq0 = (unsigned)(b * NQ + q0 + 4 * ty);

  #pragma unroll 1
  for (int jt = 0; jt < NKV / BKV; ++jt) {
    const int j0 = jt * BKV;
    __syncthreads();  // previous AV done before K/V overwrite

    // K tile transposed (scalar stores, ~4-way conflict, cold path)
    #pragma unroll
    for (int it = 0; it < (BKV * HD) / TB; ++it) {
      int idx = tid + it * TB;
      int r = idx >> 7, h = idx & 127;
      Kt[h * PK + r] = Kb[(j0 + r) * HD + h];
    }
    // V tile, row-major float4 (conflict-free)
    #pragma unroll
    for (int it = 0; it < (BKV * HD) / (TB * 4); ++it) {
      int c = tid + it * TB;
      int r = c >> 5, h4 = (c & 31) << 2;
      *reinterpret_cast<float4*>(&Vs[r * PV + h4]) =
          *reinterpret_cast<const float4*>(&Vb[(j0 + r) * HD + h4]);
    }
    __syncthreads();

    // ---- S = (scaled Q) K^T : 4x4 per thread -------------------------------
    float acc[4][4];
    #pragma unroll
    for (int i = 0; i < 4; ++i)
      #pragma unroll
      for (int jj = 0; jj < 4; ++jj) acc[i][jj] = 0.f;

    const float* qp = Qt + 4 * ty;
    const float* kp = Kt + 4 * tx;
    #pragma unroll 8
    for (int k = 0; k < HD; ++k) {
      float4 q4 = *reinterpret_cast<const float4*>(qp + k * PQ);
      float4 k4 = *reinterpret_cast<const float4*>(kp + k * PK);
      float qa[4] = {q4.x, q4.y, q4.z, q4.w};
      float ka[4] = {k4.x, k4.y, k4.z, k4.w};
      #pragma unroll
      for (int i = 0; i < 4; ++i)
        #pragma unroll
        for (int jj = 0; jj < 4; ++jj)
          acc[i][jj] = fmaf(qa[i], ka[jj], acc[i][jj]);
    }

    // ---- online softmax + dropout mask ------------------------------------
    const unsigned colbase = (unsigned)(j0 + 4 * tx);
    #pragma unroll
    for (int i = 0; i < 4; ++i) {
      float mx = fmaxf(fmaxf(acc[i][0], acc[i][1]), fmaxf(acc[i][2], acc[i][3]));
      #pragma unroll
      for (int s = 1; s < 16; s <<= 1)
        mx = fmaxf(mx, __shfl_xor_sync(0xffffffffu, mx, s));
      float mnew = fmaxf(m[i], mx);
      float corr = __expf(m[i] - mnew);
      sc[i] = corr;
      float p0 = __expf(acc[i][0] - mnew);
      float p1 = __expf(acc[i][1] - mnew);
      float p2 = __expf(acc[i][2] - mnew);
      float p3 = __expf(acc[i][3] - mnew);
      float rs = (p0 + p1) + (p2 + p3);   // denominator is UNmasked
      #pragma unroll
      for (int s = 1; s < 16; s <<= 1)
        rs += __shfl_xor_sync(0xffffffffu, rs, s);
      l[i] = l[i] * corr + rs;
      m[i] = mnew;

      unsigned base = (gq0 + (unsigned)i) * (unsigned)NKV + colbase;
      float4 pv;
      pv.x = keep_mask(base + 0u) ? p0 : 0.f;
      pv.y = keep_mask(base + 1u) ? p1 : 0.f;
      pv.z = keep_mask(base + 2u) ? p2 : 0.f;
      pv.w = keep_mask(base + 3u) ? p3 : 0.f;
      *reinterpret_cast<float4*>(&Ps[(4 * ty + i) * PP + 4 * tx]) = pv;
    }
    __syncthreads();

    // ---- O = O*corr + P V : 4x8 per thread --------------------------------
    #pragma unroll
    for (int i = 0; i < 4; ++i) {
      float c_ = sc[i];
      #pragma unroll
      for (int h = 0; h < 8; ++h) O[i][h] *= c_;
    }
    #pragma unroll 2
    for (int j4 = 0; j4 < BKV; j4 += 4) {
      float pr[4][4];
      #pragma unroll
      for (int i = 0; i < 4; ++i)
        *reinterpret_cast<float4*>(pr[i]) =
            *reinterpret_cast<const float4*>(&Ps[(4 * ty + i) * PP + j4]);
      #pragma unroll
      for (int jj = 0; jj < 4; ++jj) {
        const float* vrow = &Vs[(j4 + jj) * PV + 8 * tx];
        float4 v0 = *reinterpret_cast<const float4*>(vrow);
        float4 v1 = *reinterpret_cast<const float4*>(vrow + 4);
        float va[8] = {v0.x, v0.y, v0.z, v0.w, v1.x, v1.y, v1.z, v1.w};
        #pragma unroll
        for (int i = 0; i < 4; ++i) {
          float p = pr[i][jj];
          #pragma unroll
          for (int h = 0; h < 8; ++h)
            O[i][h] = fmaf(p, va[h], O[i][h]);
        }
      }
    }
  }

  // ---- epilogue: /(l * (1-p_drop)), coalesced float4 stores ----------------
  #pragma unroll
  for (int i = 0; i < 4; ++i) {
    float inv = 1.0f / (l[i] * 0.9f);
    float4 o0, o1;
    o0.x = O[i][0] * inv; o0.y = O[i][1] * inv;
    o0.z = O[i][2] * inv; o0.w = O[i][3] * inv;
    o1.x = O[i][4] * inv; o1.y = O[i][5] * inv;
    o1.z = O[i][6] * inv; o1.w = O[i][7] * inv;
    float* orow = Og + ((size_t)(b * NQ + q0 + 4 * ty + i)) * HD + 8 * tx;
    *reinterpret_cast<float4*>(orow)     = o0;
    *reinterpret_cast<float4*>(orow + 4) = o1;
  }
}

extern "C" void kernel_launch(void* const* d_in, const int* in_sizes, int n_in,
                              void* d_out, int out_size) {
  const float* Q = (const float*)d_in[0];
  const float* K = (const float*)d_in[1];
  const float* V = (const float*)d_in[2];
  float* O = (float*)d_out;
  (void)in_sizes; (void)n_in; (void)out_size;

  size_t shbytes = (size_t)SMEM_FLOATS * sizeof(float);  // 171,008 B
  cudaFuncSetAttribute(Model_56358560858161_kernel,
                       cudaFuncAttributeMaxDynamicSharedMemorySize,
                       (int)shbytes);
  Model_56358560858161_kernel<<<128, TB, shbytes>>>(Q, K, V, O);
}

// round 3
// speedup vs baseline: 1.0670x; 1.0670x over previous
#include <cuda_runtime.h>
#include <cstdint>

// Attention with exact JAX threefry dropout (partitionable path), fp32
// flash-attention style, GEMM microkernels on packed fma.rn.f32x2 (FFMA2).
// B=4, Q=4096, NKV=4096, H=128. scale = +sqrt(128).
//
// Grid: 128 CTAs = 4 batches x 32 q-tiles of 128 rows. 512 threads.
// Per KV tile (64 rows): S = Q K^T (4x4 microtile / thread, col-pair packed),
// online softmax with register-resident per-row stats, threefry dropout mask
// on P, then O += P V (4x8 microtile / thread, h-pair packed).

#define TB   512
#define BQ   128
#define BKV  64
#define HD   128
#define NKV  4096
#define NQ   4096

// smem pitches (floats): 16B-aligned LDS.128, low bank conflicts
#define PQ   132
#define PK   68
#define PV   132
#define PP   68

#define SMEM_FLOATS (128*PQ + 128*PK + BKV*PV + BQ*PP)

typedef unsigned long long u64;

// ---- packed f32x2 helpers (ptxas will not auto-fuse; PTX only) -------------
__device__ __forceinline__ u64 ffma2(u64 a, u64 b, u64 c) {
  u64 d; asm("fma.rn.f32x2 %0, %1, %2, %3;" : "=l"(d) : "l"(a), "l"(b), "l"(c));
  return d;
}
__device__ __forceinline__ u64 fmul2(u64 a, u64 b) {
  u64 d; asm("mul.rn.f32x2 %0, %1, %2;" : "=l"(d) : "l"(a), "l"(b));
  return d;
}
__device__ __forceinline__ u64 bcast2(float x) {
  u64 d; asm("mov.b64 %0, {%1, %1};" : "=l"(d) : "f"(x));
  return d;
}
__device__ __forceinline__ float2 unpack2(u64 v) {
  float2 r; asm("mov.b64 {%0, %1}, %2;" : "=f"(r.x), "=f"(r.y) : "l"(v));
  return r;
}

// ---------------------------------------------------------------------------
// JAX threefry2x32-20, key = (0, 42), PARTITIONABLE layout:
// counter (hi, lo) = (0, i); bits = x0_out ^ x1_out; keep <=> (bits>>9) < 7549747
// ---------------------------------------------------------------------------
__device__ __forceinline__ unsigned keep_mask(unsigned idx) {
  const unsigned ks1 = 42u;
  const unsigned ks2 = 0x1BD11BDAu ^ 42u;
  unsigned x0 = 0u;
  unsigned x1 = idx + ks1;
#define TFR(r) { x0 += x1; x1 = __funnelshift_l(x1, x1, (r)); x1 ^= x0; }
  TFR(13) TFR(15) TFR(26) TFR(6)
  x0 += ks1; x1 += ks2 + 1u;
  TFR(17) TFR(29) TFR(16) TFR(24)
  x0 += ks2; x1 += 2u;
  TFR(13) TFR(15) TFR(26) TFR(6)
  x1 += ks1 + 3u;
  TFR(17) TFR(29) TFR(16) TFR(24)
  x0 += ks1; x1 += ks2 + 4u;
  TFR(13) TFR(15) TFR(26) TFR(6)
  x0 += ks2; x1 += 5u;
#undef TFR
  unsigned bits = x0 ^ x1;
  return (bits >> 9) < 7549747u;
}

__global__ void __launch_bounds__(TB, 1)
Model_56358560858161_kernel(const float* __restrict__ Qg,
                            const float* __restrict__ Kg,
                            const float* __restrict__ Vg,
                            float* __restrict__ Og)
{
  extern __shared__ float smem[];
  float* Qt = smem;                 // [HD][PQ]  Q^T, pre-scaled by sqrt(128)
  float* Kt = Qt + 128 * PQ;        // [HD][PK]  K^T (tile)
  float* Vs = Kt + 128 * PK;        // [BKV][PV] V   (tile)
  float* Ps = Vs + BKV * PV;        // [BQ][PP]  masked probabilities

  const int tid = threadIdx.x;
  const int ty  = tid >> 4;         // 0..31  -> rows 4*ty..4*ty+3
  const int tx  = tid & 15;         // 0..15  -> S cols 4*tx.., AV cols 8*tx..
  const int b   = blockIdx.x >> 5;
  const int q0  = (blockIdx.x & 31) * BQ;

  const float* Qb = Qg + (size_t)b * NQ  * HD;
  const float* Kb = Kg + (size_t)b * NKV * HD;
  const float* Vb = Vg + (size_t)b * NKV * HD;

  const float SCALE = 11.3137084989847603904f;  // sqrt(128)

  // ---- load Q tile, transposed + pre-scaled --------------------------------
  #pragma unroll
  for (int it = 0; it < (BQ * HD) / TB; ++it) {
    int idx = tid + it * TB;
    int r = idx >> 7, h = idx & 127;
    Qt[h * PQ + r] = Qb[(q0 + r) * HD + h] * SCALE;
  }

  float m[4], l[4], sc[4];
  u64 Op[4][4];                     // O accumulator, h-pair packed
  #pragma unroll
  for (int i = 0; i < 4; ++i) {
    m[i] = -1e30f; l[i] = 0.f;
    #pragma unroll
    for (int h = 0; h < 4; ++h) Op[i][h] = 0ull;
  }

  const unsigned gq0 = (unsigned)(b * NQ + q0 + 4 * ty);

  #pragma unroll 1
  for (int jt = 0; jt < NKV / BKV; ++jt) {
    const int j0 = jt * BKV;
    __syncthreads();  // previous AV done before K/V overwrite

    // K tile transposed (scalar stores, cold path)
    #pragma unroll
    for (int it = 0; it < (BKV * HD) / TB; ++it) {
      int idx = tid + it * TB;
      int r = idx >> 7, h = idx & 127;
      Kt[h * PK + r] = Kb[(j0 + r) * HD + h];
    }
    // V tile, row-major float4 (conflict-free)
    #pragma unroll
    for (int it = 0; it < (BKV * HD) / (TB * 4); ++it) {
      int c = tid + it * TB;
      int r = c >> 5, h4 = (c & 31) << 2;
      *reinterpret_cast<float4*>(&Vs[r * PV + h4]) =
          *reinterpret_cast<const float4*>(&Vb[(j0 + r) * HD + h4]);
    }
    __syncthreads();

    // ---- S = (scaled Q) K^T : 4 rows x (2 col-pairs) per thread, FFMA2 ----
    u64 accp[4][2];
    #pragma unroll
    for (int i = 0; i < 4; ++i) { accp[i][0] = 0ull; accp[i][1] = 0ull; }

    const float* qp = Qt + 4 * ty;
    const float* kp = Kt + 4 * tx;
    #pragma unroll 8
    for (int k = 0; k < HD; ++k) {
      float4 q4 = *reinterpret_cast<const float4*>(qp + k * PQ);
      ulonglong2 k2 = *reinterpret_cast<const ulonglong2*>(kp + k * PK);
      u64 qb0 = bcast2(q4.x), qb1 = bcast2(q4.y);
      u64 qb2 = bcast2(q4.z), qb3 = bcast2(q4.w);
      accp[0][0] = ffma2(qb0, k2.x, accp[0][0]);
      accp[0][1] = ffma2(qb0, k2.y, accp[0][1]);
      accp[1][0] = ffma2(qb1, k2.x, accp[1][0]);
      accp[1][1] = ffma2(qb1, k2.y, accp[1][1]);
      accp[2][0] = ffma2(qb2, k2.x, accp[2][0]);
      accp[2][1] = ffma2(qb2, k2.y, accp[2][1]);
      accp[3][0] = ffma2(qb3, k2.x, accp[3][0]);
      accp[3][1] = ffma2(qb3, k2.y, accp[3][1]);
    }

    // ---- online softmax + dropout mask ------------------------------------
    const unsigned colbase = (unsigned)(j0 + 4 * tx);
    #pragma unroll
    for (int i = 0; i < 4; ++i) {
      float2 a01 = unpack2(accp[i][0]);
      float2 a23 = unpack2(accp[i][1]);
      float mx = fmaxf(fmaxf(a01.x, a01.y), fmaxf(a23.x, a23.y));
      #pragma unroll
      for (int s = 1; s < 16; s <<= 1)
        mx = fmaxf(mx, __shfl_xor_sync(0xffffffffu, mx, s));
      float mnew = fmaxf(m[i], mx);
      float corr = __expf(m[i] - mnew);
      sc[i] = corr;
      float p0 = __expf(a01.x - mnew);
      float p1 = __expf(a01.y - mnew);
      float p2 = __expf(a23.x - mnew);
      float p3 = __expf(a23.y - mnew);
      float rs = (p0 + p1) + (p2 + p3);   // denominator is UNmasked
      #pragma unroll
      for (int s = 1; s < 16; s <<= 1)
        rs += __shfl_xor_sync(0xffffffffu, rs, s);
      l[i] = l[i] * corr + rs;
      m[i] = mnew;

      unsigned base = (gq0 + (unsigned)i) * (unsigned)NKV + colbase;
      float4 pv;
      pv.x = keep_mask(base + 0u) ? p0 : 0.f;
      pv.y = keep_mask(base + 1u) ? p1 : 0.f;
      pv.z = keep_mask(base + 2u) ? p2 : 0.f;
      pv.w = keep_mask(base + 3u) ? p3 : 0.f;
      *reinterpret_cast<float4*>(&Ps[(4 * ty + i) * PP + 4 * tx]) = pv;
    }
    __syncthreads();

    // ---- O = O*corr + P V : 4 rows x (4 h-pairs) per thread, FFMA2 --------
    #pragma unroll
    for (int i = 0; i < 4; ++i) {
      u64 c2 = bcast2(sc[i]);
      #pragma unroll
      for (int h = 0; h < 4; ++h) Op[i][h] = fmul2(Op[i][h], c2);
    }
    #pragma unroll 2
    for (int j4 = 0; j4 < BKV; j4 += 4) {
      float pr[4][4];
      #pragma unroll
      for (int i = 0; i < 4; ++i)
        *reinterpret_cast<float4*>(pr[i]) =
            *reinterpret_cast<const float4*>(&Ps[(4 * ty + i) * PP + j4]);
      #pragma unroll
      for (int jj = 0; jj < 4; ++jj) {
        const float* vrow = &Vs[(j4 + jj) * PV + 8 * tx];
        ulonglong2 va = *reinterpret_cast<const ulonglong2*>(vrow);
        ulonglong2 vb = *reinterpret_cast<const ulonglong2*>(vrow + 4);
        #pragma unroll
        for (int i = 0; i < 4; ++i) {
          u64 pb = bcast2(pr[i][jj]);
          Op[i][0] = ffma2(pb, va.x, Op[i][0]);
          Op[i][1] = ffma2(pb, va.y, Op[i][1]);
          Op[i][2] = ffma2(pb, vb.x, Op[i][2]);
          Op[i][3] = ffma2(pb, vb.y, Op[i][3]);
        }
      }
    }
  }

  // ---- epilogue: /(l * (1-p_drop)), coalesced 16B stores -------------------
  #pragma unroll
  for (int i = 0; i < 4; ++i) {
    float inv = 1.0f / (l[i] * 0.9f);
    u64 inv2 = bcast2(inv);
    ulonglong2 s0, s1;
    s0.x = fmul2(Op[i][0], inv2);
    s0.y = fmul2(Op[i][1], inv2);
    s1.x = fmul2(Op[i][2], inv2);
    s1.y = fmul2(Op[i][3], inv2);
    float* orow = Og + ((size_t)(b * NQ + q0 + 4 * ty + i)) * HD + 8 * tx;
    *reinterpret_cast<ulonglong2*>(orow)     = s0;
    *reinterpret_cast<ulonglong2*>(orow + 4) = s1;
  }
}

extern "C" void kernel_launch(void* const* d_in, const int* in_sizes, int n_in,
                              void* d_out, int out_size) {
  const float* Q = (const float*)d_in[0];
  const float* K = (const float*)d_in[1];
  const float* V = (const float*)d_in[2];
  float* O = (float*)d_out;
  (void)in_sizes; (void)n_in; (void)out_size;

  size_t shbytes = (size_t)SMEM_FLOATS * sizeof(float);  // 171,008 B
  cudaFuncSetAttribute(Model_56358560858161_kernel,
                       cudaFuncAttributeMaxDynamicSharedMemorySize,
                       (int)shbytes);
  Model_56358560858161_kernel<<<128, TB, shbytes>>>(Q, K, V, O);
}

// round 4
// speedup vs baseline: 1.0977x; 1.0288x over previous
#include <cuda_runtime.h>
#include <cstdint>

// fp32 flash-attention with exact JAX threefry dropout (partitionable path).
// B=4, Q=4096, NKV=4096, H=128. scale = +sqrt(128) (applied post-dot).
//
// Round 4: cp.async pipelined K/V (K double-buffered), transpose-free S phase
// (row-dot-products, h-parity-packed FFMA2, zero broadcasts in S inner loop),
// column ownership striped tx+16*jj for low-conflict K row reads.

#define TB   512
#define BQ   128
#define BKV  64
#define HD   128
#define NKV  4096
#define NQ   4096

#define PQR  128   // Q row pitch (floats)
#define PKR  132   // K row pitch (lane stride 132w ≡ 4 mod 32 -> 2-way max)
#define PVR  128   // V row pitch
#define PPR  64    // P row pitch

// smem floats: Q + 2*K + V + P
#define SMEM_FLOATS (BQ*PQR + 2*BKV*PKR + BKV*PVR + BQ*PPR)

typedef unsigned long long u64;

// ---- packed f32x2 helpers ---------------------------------------------------
__device__ __forceinline__ u64 ffma2(u64 a, u64 b, u64 c) {
  u64 d; asm("fma.rn.f32x2 %0, %1, %2, %3;" : "=l"(d) : "l"(a), "l"(b), "l"(c));
  return d;
}
__device__ __forceinline__ u64 fmul2(u64 a, u64 b) {
  u64 d; asm("mul.rn.f32x2 %0, %1, %2;" : "=l"(d) : "l"(a), "l"(b));
  return d;
}
__device__ __forceinline__ u64 bcast2(float x) {
  u64 d; asm("mov.b64 %0, {%1, %1};" : "=l"(d) : "f"(x));
  return d;
}
__device__ __forceinline__ float2 unpack2(u64 v) {
  float2 r; asm("mov.b64 {%0, %1}, %2;" : "=f"(r.x), "=f"(r.y) : "l"(v));
  return r;
}

// ---- cp.async ---------------------------------------------------------------
__device__ __forceinline__ void cpa16(uint32_t dst, const float* src) {
  asm volatile("cp.async.cg.shared.global [%0], [%1], 16;" :: "r"(dst), "l"(src));
}
__device__ __forceinline__ void cpa_commit() {
  asm volatile("cp.async.commit_group;");
}
__device__ __forceinline__ void cpa_wait_all() {
  asm volatile("cp.async.wait_group 0;");
}

// ---------------------------------------------------------------------------
// JAX threefry2x32-20, key = (0, 42), PARTITIONABLE layout:
// counter (hi,lo) = (0,i); bits = x0^x1; keep <=> (bits>>9) < 7549747
// ---------------------------------------------------------------------------
__device__ __forceinline__ unsigned keep_mask(unsigned idx) {
  const unsigned ks1 = 42u;
  const unsigned ks2 = 0x1BD11BDAu ^ 42u;
  unsigned x0 = 0u;
  unsigned x1 = idx + ks1;
#define TFR(r) { x0 += x1; x1 = __funnelshift_l(x1, x1, (r)); x1 ^= x0; }
  TFR(13) TFR(15) TFR(26) TFR(6)
  x0 += ks1; x1 += ks2 + 1u;
  TFR(17) TFR(29) TFR(16) TFR(24)
  x0 += ks2; x1 += 2u;
  TFR(13) TFR(15) TFR(26) TFR(6)
  x1 += ks1 + 3u;
  TFR(17) TFR(29) TFR(16) TFR(24)
  x0 += ks1; x1 += ks2 + 4u;
  TFR(13) TFR(15) TFR(26) TFR(6)
  x0 += ks2; x1 += 5u;
#undef TFR
  unsigned bits = x0 ^ x1;
  return (bits >> 9) < 7549747u;
}

__global__ void __launch_bounds__(TB, 1)
Model_56358560858161_kernel(const float* __restrict__ Qg,
                            const float* __restrict__ Kg,
                            const float* __restrict__ Vg,
                            float* __restrict__ Og)
{
  extern __shared__ float smem[];
  float* Qs  = smem;                       // [BQ][PQR] row-major
  float* Kb0 = Qs  + BQ * PQR;             // [BKV][PKR] buffer 0
  float* Kb1 = Kb0 + BKV * PKR;            // [BKV][PKR] buffer 1
  float* Vs  = Kb1 + BKV * PKR;            // [BKV][PVR]
  float* Ps  = Vs  + BKV * PVR;            // [BQ][PPR]

  const uint32_t smem_u32 = (uint32_t)__cvta_generic_to_shared(smem);
  const uint32_t Qa  = smem_u32;
  const uint32_t Ka0 = Qa  + BQ * PQR * 4;
  const uint32_t Ka1 = Ka0 + BKV * PKR * 4;
  const uint32_t Va  = Ka1 + BKV * PKR * 4;

  const int tid = threadIdx.x;
  const int ty  = tid >> 4;         // 0..31 -> q rows 4*ty..4*ty+3
  const int tx  = tid & 15;         // 0..15 -> S cols {tx + 16*jj}
  const int b   = blockIdx.x >> 5;
  const int q0  = (blockIdx.x & 31) * BQ;

  const float* Qb = Qg + (size_t)b * NQ  * HD;
  const float* Kb = Kg + (size_t)b * NKV * HD;
  const float* Vb = Vg + (size_t)b * NKV * HD;

  const float SCALE = 11.3137084989847603904f;  // sqrt(128)

  // ---- prologue: cp.async Q (whole tile) + K tile 0 ------------------------
  #pragma unroll
  for (int it = 0; it < (BQ * HD) / (TB * 4); ++it) {   // 8 chunks/thread
    int c = tid + it * TB;
    int r = c >> 5, col = c & 31;                        // 32 x 16B per row
    cpa16(Qa + (r * PQR + col * 4) * 4, Qb + (q0 + r) * HD + col * 4);
  }
  #pragma unroll
  for (int it = 0; it < (BKV * HD) / (TB * 4); ++it) {  // 4 chunks/thread
    int c = tid + it * TB;
    int r = c >> 5, col = c & 31;
    cpa16(Ka0 + (r * PKR + col * 4) * 4, Kb + r * HD + col * 4);
  }
  cpa_commit();

  float m[4], l[4], sc[4];
  u64 Op[4][4];
  #pragma unroll
  for (int i = 0; i < 4; ++i) {
    m[i] = -1e30f; l[i] = 0.f;
    #pragma unroll
    for (int h = 0; h < 4; ++h) Op[i][h] = 0ull;
  }

  const unsigned gq0 = (unsigned)(b * NQ + q0 + 4 * ty);

  cpa_wait_all();
  __syncthreads();

  #pragma unroll 1
  for (int jt = 0; jt < NKV / BKV; ++jt) {
    const int j0 = jt * BKV;
    const float*  Kcur = (jt & 1) ? Kb1 : Kb0;
    const uint32_t Knxt = (jt & 1) ? Ka0 : Ka1;

    // ---- issue cp.async: V(jt) and K(jt+1) -------------------------------
    #pragma unroll
    for (int it = 0; it < (BKV * HD) / (TB * 4); ++it) {
      int c = tid + it * TB;
      int r = c >> 5, col = c & 31;
      cpa16(Va + (r * PVR + col * 4) * 4, Vb + (j0 + r) * HD + col * 4);
    }
    if (jt + 1 < NKV / BKV) {
      #pragma unroll
      for (int it = 0; it < (BKV * HD) / (TB * 4); ++it) {
        int c = tid + it * TB;
        int r = c >> 5, col = c & 31;
        cpa16(Knxt + (r * PKR + col * 4) * 4, Kb + (j0 + BKV + r) * HD + col * 4);
      }
    }
    cpa_commit();

    // ---- S = Q K^T : rows 4ty+i, cols tx+16jj; h-parity-packed FFMA2 ------
    u64 acc2[4][4];
    #pragma unroll
    for (int i = 0; i < 4; ++i)
      #pragma unroll
      for (int jj = 0; jj < 4; ++jj) acc2[i][jj] = 0ull;

    const float* qp = Qs + (4 * ty) * PQR;
    const float* kp = Kcur + tx * PKR;
    #pragma unroll 4
    for (int h4 = 0; h4 < HD; h4 += 4) {
      ulonglong2 q[4], k[4];
      #pragma unroll
      for (int i = 0; i < 4; ++i)
        q[i] = *reinterpret_cast<const ulonglong2*>(qp + i * PQR + h4);
      #pragma unroll
      for (int jj = 0; jj < 4; ++jj)
        k[jj] = *reinterpret_cast<const ulonglong2*>(kp + jj * 16 * PKR + h4);
      #pragma unroll
      for (int i = 0; i < 4; ++i)
        #pragma unroll
        for (int jj = 0; jj < 4; ++jj) {
          acc2[i][jj] = ffma2(q[i].x, k[jj].x, acc2[i][jj]);
          acc2[i][jj] = ffma2(q[i].y, k[jj].y, acc2[i][jj]);
        }
    }

    // ---- online softmax + dropout mask ------------------------------------
    #pragma unroll
    for (int i = 0; i < 4; ++i) {
      float s0, s1, s2, s3;
      { float2 a = unpack2(acc2[i][0]); s0 = (a.x + a.y) * SCALE; }
      { float2 a = unpack2(acc2[i][1]); s1 = (a.x + a.y) * SCALE; }
      { float2 a = unpack2(acc2[i][2]); s2 = (a.x + a.y) * SCALE; }
      { float2 a = unpack2(acc2[i][3]); s3 = (a.x + a.y) * SCALE; }
      float mx = fmaxf(fmaxf(s0, s1), fmaxf(s2, s3));
      #pragma unroll
      for (int s = 1; s < 16; s <<= 1)
        mx = fmaxf(mx, __shfl_xor_sync(0xffffffffu, mx, s));
      float mnew = fmaxf(m[i], mx);
      float corr = __expf(m[i] - mnew);
      sc[i] = corr;
      float p0 = __expf(s0 - mnew);
      float p1 = __expf(s1 - mnew);
      float p2 = __expf(s2 - mnew);
      float p3 = __expf(s3 - mnew);
      float rs = (p0 + p1) + (p2 + p3);   // denominator is UNmasked
      #pragma unroll
      for (int s = 1; s < 16; s <<= 1)
        rs += __shfl_xor_sync(0xffffffffu, rs, s);
      l[i] = l[i] * corr + rs;
      m[i] = mnew;

      // dropout mask; cols are tx + 16*jj
      unsigned base = (gq0 + (unsigned)i) * (unsigned)NKV + (unsigned)(j0 + tx);
      float* prow = &Ps[(4 * ty + i) * PPR + tx];
      prow[0]  = keep_mask(base +  0u) ? p0 : 0.f;
      prow[16] = keep_mask(base + 16u) ? p1 : 0.f;
      prow[32] = keep_mask(base + 32u) ? p2 : 0.f;
      prow[48] = keep_mask(base + 48u) ? p3 : 0.f;
    }

    cpa_wait_all();     // V(jt) (+K(jt+1)) arrived
    __syncthreads();    // Ps + V visible to all

    // ---- O = O*corr + P V : 4 rows x (4 h-pairs), FFMA2 -------------------
    #pragma unroll
    for (int i = 0; i < 4; ++i) {
      u64 c2 = bcast2(sc[i]);
      #pragma unroll
      for (int h = 0; h < 4; ++h) Op[i][h] = fmul2(Op[i][h], c2);
    }
    #pragma unroll 2
    for (int j4 = 0; j4 < BKV; j4 += 4) {
      float pr[4][4];
      #pragma unroll
      for (int i = 0; i < 4; ++i)
        *reinterpret_cast<float4*>(pr[i]) =
            *reinterpret_cast<const float4*>(&Ps[(4 * ty + i) * PPR + j4]);
      #pragma unroll
      for (int jj = 0; jj < 4; ++jj) {
        const float* vrow = &Vs[(j4 + jj) * PVR + 8 * tx];
        ulonglong2 va = *reinterpret_cast<const ulonglong2*>(vrow);
        ulonglong2 vb = *reinterpret_cast<const ulonglong2*>(vrow + 4);
        #pragma unroll
        for (int i = 0; i < 4; ++i) {
          u64 pb = bcast2(pr[i][jj]);
          Op[i][0] = ffma2(pb, va.x, Op[i][0]);
          Op[i][1] = ffma2(pb, va.y, Op[i][1]);
          Op[i][2] = ffma2(pb, vb.x, Op[i][2]);
          Op[i][3] = ffma2(pb, vb.y, Op[i][3]);
        }
      }
    }

    __syncthreads();    // everyone done with Vs/Ps/Kcur before overwrite
  }

  // ---- epilogue: /(l * (1-p_drop)), coalesced 16B stores -------------------
  #pragma unroll
  for (int i = 0; i < 4; ++i) {
    float inv = 1.0f / (l[i] * 0.9f);
    u64 inv2 = bcast2(inv);
    ulonglong2 s0, s1;
    s0.x = fmul2(Op[i][0], inv2);
    s0.y = fmul2(Op[i][1], inv2);
    s1.x = fmul2(Op[i][2], inv2);
    s1.y = fmul2(Op[i][3], inv2);
    float* orow = Og + ((size_t)(b * NQ + q0 + 4 * ty + i)) * HD + 8 * tx;
    *reinterpret_cast<ulonglong2*>(orow)     = s0;
    *reinterpret_cast<ulonglong2*>(orow + 4) = s1;
  }
}

extern "C" void kernel_launch(void* const* d_in, const int* in_sizes, int n_in,
                              void* d_out, int out_size) {
  const float* Q = (const float*)d_in[0];
  const float* K = (const float*)d_in[1];
  const float* V = (const float*)d_in[2];
  float* O = (float*)d_out;
  (void)in_sizes; (void)n_in; (void)out_size;

  size_t shbytes = (size_t)SMEM_FLOATS * sizeof(float);  // 198,656 B
  cudaFuncSetAttribute(Model_56358560858161_kernel,
                       cudaFuncAttributeMaxDynamicSharedMemorySize,
                       (int)shbytes);
  Model_56358560858161_kernel<<<128, TB, shbytes>>>(Q, K, V, O);
}

// round 5
// speedup vs baseline: 1.1061x; 1.0076x over previous
#include <cuda_runtime.h>
#include <cstdint>

// fp32 flash-attention with exact JAX threefry dropout (partitionable path).
// B=4, Q=4096, NKV=4096, H=128. scale = +sqrt(128) (applied post-dot).
//
// Round 4: cp.async pipelined K/V (K double-buffered), transpose-free S phase
// (row-dot-products, h-parity-packed FFMA2, zero broadcasts in S inner loop),
// column ownership striped tx+16*jj for low-conflict K row reads.

#define TB   512
#define BQ   128
#define BKV  64
#define HD   128
#define NKV  4096
#define NQ   4096

#define PQR  128   // Q row pitch (floats)
#define PKR  132   // K row pitch (lane stride 132w ≡ 4 mod 32 -> 2-way max)
#define PVR  128   // V row pitch
#define PPR  64    // P row pitch

// smem floats: Q + 2*K + V + P
#define SMEM_FLOATS (BQ*PQR + 2*BKV*PKR + BKV*PVR + BQ*PPR)

typedef unsigned long long u64;

// ---- packed f32x2 helpers ---------------------------------------------------
__device__ __forceinline__ u64 ffma2(u64 a, u64 b, u64 c) {
  u64 d; asm("fma.rn.f32x2 %0, %1, %2, %3;" : "=l"(d) : "l"(a), "l"(b), "l"(c));
  return d;
}
__device__ __forceinline__ u64 fmul2(u64 a, u64 b) {
  u64 d; asm("mul.rn.f32x2 %0, %1, %2;" : "=l"(d) : "l"(a), "l"(b));
  return d;
}
__device__ __forceinline__ u64 bcast2(float x) {
  u64 d; asm("mov.b64 %0, {%1, %1};" : "=l"(d) : "f"(x));
  return d;
}
__device__ __forceinline__ float2 unpack2(u64 v) {
  float2 r; asm("mov.b64 {%0, %1}, %2;" : "=f"(r.x), "=f"(r.y) : "l"(v));
  return r;
}

// ---- cp.async ---------------------------------------------------------------
__device__ __forceinline__ void cpa16(uint32_t dst, const float* src) {
  asm volatile("cp.async.cg.shared.global [%0], [%1], 16;" :: "r"(dst), "l"(src));
}
__device__ __forceinline__ void cpa_commit() {
  asm volatile("cp.async.commit_group;");
}
__device__ __forceinline__ void cpa_wait_all() {
  asm volatile("cp.async.wait_group 0;");
}

// ---------------------------------------------------------------------------
// JAX threefry2x32-20, key = (0, 42), PARTITIONABLE layout:
// counter (hi,lo) = (0,i); bits = x0^x1; keep <=> (bits>>9) < 7549747
// ---------------------------------------------------------------------------
__device__ __forceinline__ unsigned keep_mask(unsigned idx) {
  const unsigned ks1 = 42u;
  const unsigned ks2 = 0x1BD11BDAu ^ 42u;
  unsigned x0 = 0u;
  unsigned x1 = idx + ks1;
#define TFR(r) { x0 += x1; x1 = __funnelshift_l(x1, x1, (r)); x1 ^= x0; }
  TFR(13) TFR(15) TFR(26) TFR(6)
  x0 += ks1; x1 += ks2 + 1u;
  TFR(17) TFR(29) TFR(16) TFR(24)
  x0 += ks2; x1 += 2u;
  TFR(13) TFR(15) TFR(26) TFR(6)
  x1 += ks1 + 3u;
  TFR(17) TFR(29) TFR(16) TFR(24)
  x0 += ks1; x1 += ks2 + 4u;
  TFR(13) TFR(15) TFR(26) TFR(6)
  x0 += ks2; x1 += 5u;
#undef TFR
  unsigned bits = x0 ^ x1;
  return (bits >> 9) < 7549747u;
}

__global__ void __launch_bounds__(TB, 1)
Model_56358560858161_kernel(const float* __restrict__ Qg,
                            const float* __restrict__ Kg,
                            const float* __restrict__ Vg,
                            float* __restrict__ Og)
{
  extern __shared__ float smem[];
  float* Qs  = smem;                       // [BQ][PQR] row-major
  float* Kb0 = Qs  + BQ * PQR;             // [BKV][PKR] buffer 0
  float* Kb1 = Kb0 + BKV * PKR;            // [BKV][PKR] buffer 1
  float* Vs  = Kb1 + BKV * PKR;            // [BKV][PVR]
  float* Ps  = Vs  + BKV * PVR;            // [BQ][PPR]

  const uint32_t smem_u32 = (uint32_t)__cvta_generic_to_shared(smem);
  const uint32_t Qa  = smem_u32;
  const uint32_t Ka0 = Qa  + BQ * PQR * 4;
  const uint32_t Ka1 = Ka0 + BKV * PKR * 4;
  const uint32_t Va  = Ka1 + BKV * PKR * 4;

  const int tid = threadIdx.x;
  const int ty  = tid >> 4;         // 0..31 -> q rows 4*ty..4*ty+3
  const int tx  = tid & 15;         // 0..15 -> S cols {tx + 16*jj}
  const int b   = blockIdx.x >> 5;
  const int q0  = (blockIdx.x & 31) * BQ;

  const float* Qb = Qg + (size_t)b * NQ  * HD;
  const float* Kb = Kg + (size_t)b * NKV * HD;
  const float* Vb = Vg + (size_t)b * NKV * HD;

  const float SCALE = 11.3137084989847603904f;  // sqrt(128)

  // ---- prologue: cp.async Q (whole tile) + K tile 0 ------------------------
  #pragma unroll
  for (int it = 0; it < (BQ * HD) / (TB * 4); ++it) {   // 8 chunks/thread
    int c = tid + it * TB;
    int r = c >> 5, col = c & 31;                        // 32 x 16B per row
    cpa16(Qa + (r * PQR + col * 4) * 4, Qb + (q0 + r) * HD + col * 4);
  }
  #pragma unroll
  for (int it = 0; it < (BKV * HD) / (TB * 4); ++it) {  // 4 chunks/thread
    int c = tid + it * TB;
    int r = c >> 5, col = c & 31;
    cpa16(Ka0 + (r * PKR + col * 4) * 4, Kb + r * HD + col * 4);
  }
  cpa_commit();

  float m[4], l[4], sc[4];
  u64 Op[4][4];
  #pragma unroll
  for (int i = 0; i < 4; ++i) {
    m[i] = -1e30f; l[i] = 0.f;
    #pragma unroll
    for (int h = 0; h < 4; ++h) Op[i][h] = 0ull;
  }

  const unsigned gq0 = (unsigned)(b * NQ + q0 + 4 * ty);

  cpa_wait_all();
  __syncthreads();

  #pragma unroll 1
  for (int jt = 0; jt < NKV / BKV; ++jt) {
    const int j0 = jt * BKV;
    const float*  Kcur = (jt & 1) ? Kb1 : Kb0;
    const uint32_t Knxt = (jt & 1) ? Ka0 : Ka1;

    // ---- issue cp.async: V(jt) and K(jt+1) -------------------------------
    #pragma unroll
    for (int it = 0; it < (BKV * HD) / (TB * 4); ++it) {
      int c = tid + it * TB;
      int r = c >> 5, col = c & 31;
      cpa16(Va + (r * PVR + col * 4) * 4, Vb + (j0 + r) * HD + col * 4);
    }
    if (jt + 1 < NKV / BKV) {
      #pragma unroll
      for (int it = 0; it < (BKV * HD) / (TB * 4); ++it) {
        int c = tid + it * TB;
        int r = c >> 5, col = c & 31;
        cpa16(Knxt + (r * PKR + col * 4) * 4, Kb + (j0 + BKV + r) * HD + col * 4);
      }
    }
    cpa_commit();

    // ---- S = Q K^T : rows 4ty+i, cols tx+16jj; h-parity-packed FFMA2 ------
    u64 acc2[4][4];
    #pragma unroll
    for (int i = 0; i < 4; ++i)
      #pragma unroll
      for (int jj = 0; jj < 4; ++jj) acc2[i][jj] = 0ull;

    const float* qp = Qs + (4 * ty) * PQR;
    const float* kp = Kcur + tx * PKR;
    #pragma unroll 4
    for (int h4 = 0; h4 < HD; h4 += 4) {
      ulonglong2 q[4], k[4];
      #pragma unroll
      for (int i = 0; i < 4; ++i)
        q[i] = *reinterpret_cast<const ulonglong2*>(qp + i * PQR + h4);
      #pragma unroll
      for (int jj = 0; jj < 4; ++jj)
        k[jj] = *reinterpret_cast<const ulonglong2*>(kp + jj * 16 * PKR + h4);
      #pragma unroll
      for (int i = 0; i < 4; ++i)
        #pragma unroll
        for (int jj = 0; jj < 4; ++jj) {
          acc2[i][jj] = ffma2(q[i].x, k[jj].x, acc2[i][jj]);
          acc2[i][jj] = ffma2(q[i].y, k[jj].y, acc2[i][jj]);
        }
    }

    // ---- online softmax + dropout mask ------------------------------------
    #pragma unroll
    for (int i = 0; i < 4; ++i) {
      float s0, s1, s2, s3;
      { float2 a = unpack2(acc2[i][0]); s0 = (a.x + a.y) * SCALE; }
      { float2 a = unpack2(acc2[i][1]); s1 = (a.x + a.y) * SCALE; }
      { float2 a = unpack2(acc2[i][2]); s2 = (a.x + a.y) * SCALE; }
      { float2 a = unpack2(acc2[i][3]); s3 = (a.x + a.y) * SCALE; }
      float mx = fmaxf(fmaxf(s0, s1), fmaxf(s2, s3));
      #pragma unroll
      for (int s = 1; s < 16; s <<= 1)
        mx = fmaxf(mx, __shfl_xor_sync(0xffffffffu, mx, s));
      float mnew = fmaxf(m[i], mx);
      float corr = __expf(m[i] - mnew);
      sc[i] = corr;
      float p0 = __expf(s0 - mnew);
      float p1 = __expf(s1 - mnew);
      float p2 = __expf(s2 - mnew);
      float p3 = __expf(s3 - mnew);
      float rs = (p0 + p1) + (p2 + p3);   // denominator is UNmasked
      #pragma unroll
      for (int s = 1; s < 16; s <<= 1)
        rs += __shfl_xor_sync(0xffffffffu, rs, s);
      l[i] = l[i] * corr + rs;
      m[i] = mnew;

      // dropout mask; cols are tx + 16*jj
      unsigned base = (gq0 + (unsigned)i) * (unsigned)NKV + (unsigned)(j0 + tx);
      float* prow = &Ps[(4 * ty + i) * PPR + tx];
      prow[0]  = keep_mask(base +  0u) ? p0 : 0.f;
      prow[16] = keep_mask(base + 16u) ? p1 : 0.f;
      prow[32] = keep_mask(base + 32u) ? p2 : 0.f;
      prow[48] = keep_mask(base + 48u) ? p3 : 0.f;
    }

    cpa_wait_all();     // V(jt) (+K(jt+1)) arrived
    __syncthreads();    // Ps + V visible to all

    // ---- O = O*corr + P V : 4 rows x (4 h-pairs), FFMA2 -------------------
    #pragma unroll
    for (int i = 0; i < 4; ++i) {
      u64 c2 = bcast2(sc[i]);
      #pragma unroll
      for (int h = 0; h < 4; ++h) Op[i][h] = fmul2(Op[i][h], c2);
    }
    #pragma unroll 2
    for (int j4 = 0; j4 < BKV; j4 += 4) {
      float pr[4][4];
      #pragma unroll
      for (int i = 0; i < 4; ++i)
        *reinterpret_cast<float4*>(pr[i]) =
            *reinterpret_cast<const float4*>(&Ps[(4 * ty + i) * PPR + j4]);
      #pragma unroll
      for (int jj = 0; jj < 4; ++jj) {
        const float* vrow = &Vs[(j4 + jj) * PVR + 8 * tx];
        ulonglong2 va = *reinterpret_cast<const ulonglong2*>(vrow);
        ulonglong2 vb = *reinterpret_cast<const ulonglong2*>(vrow + 4);
        #pragma unroll
        for (int i = 0; i < 4; ++i) {
          u64 pb = bcast2(pr[i][jj]);
          Op[i][0] = ffma2(pb, va.x, Op[i][0]);
          Op[i][1] = ffma2(pb, va.y, Op[i][1]);
          Op[i][2] = ffma2(pb, vb.x, Op[i][2]);
          Op[i][3] = ffma2(pb, vb.y, Op[i][3]);
        }
      }
    }

    __syncthreads();    // everyone done with Vs/Ps/Kcur before overwrite
  }

  // ---- epilogue: /(l * (1-p_drop)), coalesced 16B stores -------------------
  #pragma unroll
  for (int i = 0; i < 4; ++i) {
    float inv = 1.0f / (l[i] * 0.9f);
    u64 inv2 = bcast2(inv);
    ulonglong2 s0, s1;
    s0.x = fmul2(Op[i][0], inv2);
    s0.y = fmul2(Op[i][1], inv2);
    s1.x = fmul2(Op[i][2], inv2);
    s1.y = fmul2(Op[i][3], inv2);
    float* orow = Og + ((size_t)(b * NQ + q0 + 4 * ty + i)) * HD + 8 * tx;
    *reinterpret_cast<ulonglong2*>(orow)     = s0;
    *reinterpret_cast<ulonglong2*>(orow + 4) = s1;
  }
}

extern "C" void kernel_launch(void* const* d_in, const int* in_sizes, int n_in,
                              void* d_out, int out_size) {
  const float* Q = (const float*)d_in[0];
  const float* K = (const float*)d_in[1];
  const float* V = (const float*)d_in[2];
  float* O = (float*)d_out;
  (void)in_sizes; (void)n_in; (void)out_size;

  size_t shbytes = (size_t)SMEM_FLOATS * sizeof(float);  // 198,656 B
  cudaFuncSetAttribute(Model_56358560858161_kernel,
                       cudaFuncAttributeMaxDynamicSharedMemorySize,
                       (int)shbytes);
  Model_56358560858161_kernel<<<128, TB, shbytes>>>(Q, K, V, O);
}

// round 7
// speedup vs baseline: 2.1761x; 1.9674x over previous
#include <cuda_runtime.h>
#include <cuda_fp16.h>
#include <cstdint>

// HMMA (mma.sync m16n8k16 fp16, fp32 acc) flash-attention with 3-term fp16
// split for fp32 accuracy, exact JAX threefry dropout.
// B=4, Q=4096, NKV=4096, H=128, scale=+sqrt(128) folded into Q.
// 128 CTAs (4 batches x 32 q-tiles of 128 rows), 512 threads = 16 warps (4x4).

#define TB  512
#define BQ  128
#define BKV 64
#define HD  128
#define NQ  4096
#define NKV 4096
#define NT  (NKV/BKV)

// f16 pitches (elements): +8 pad -> conflict-free ldmatrix
#define QP 136
#define KP 136
#define VP 72
#define PP 72

// smem byte offsets (all 128-aligned)
#define SM_QH   0u
#define SM_QL   34816u
#define SM_KH   69632u
#define SM_KL   87040u
#define SM_VTH  104448u
#define SM_VTL  122880u
#define SM_PH   141312u
#define SM_PL   159744u
#define SM_REDA 178176u
#define SM_REDB 180224u
#define SM_TOT  182272u

__device__ __forceinline__ void ldsm4(uint32_t* r, uint32_t a) {
  asm volatile("ldmatrix.sync.aligned.m8n8.x4.shared.b16 {%0,%1,%2,%3},[%4];"
               : "=r"(r[0]), "=r"(r[1]), "=r"(r[2]), "=r"(r[3]) : "r"(a));
}
// 16x16 tile fragment address for this lane (A-layout; also B via rows=n)
__device__ __forceinline__ uint32_t tadr(uint32_t base, int pitchB, int r0, int c0, int lane) {
  int rr = r0 + (lane & 7) + ((lane >> 3) & 1) * 8;
  int cc = c0 + (lane >> 4) * 8;
  return base + rr * pitchB + cc * 2;
}
__device__ __forceinline__ void mma_(float* d, const uint32_t* a, uint32_t b0, uint32_t b1) {
  asm volatile(
    "mma.sync.aligned.m16n8k16.row.col.f32.f16.f16.f32 "
    "{%0,%1,%2,%3},{%4,%5,%6,%7},{%8,%9},{%0,%1,%2,%3};"
    : "+f"(d[0]), "+f"(d[1]), "+f"(d[2]), "+f"(d[3])
    : "r"(a[0]), "r"(a[1]), "r"(a[2]), "r"(a[3]), "r"(b0), "r"(b1));
}
__device__ __forceinline__ void sts128(uint32_t a, uint32_t x, uint32_t y, uint32_t z, uint32_t w) {
  asm volatile("st.shared.v4.b32 [%0],{%1,%2,%3,%4};" :: "r"(a), "r"(x), "r"(y), "r"(z), "r"(w));
}
__device__ __forceinline__ void sts32(uint32_t a, uint32_t x) {
  asm volatile("st.shared.b32 [%0],%1;" :: "r"(a), "r"(x));
}
// split two fp32 -> packed half2 hi + half2 residual
__device__ __forceinline__ void splith(float a, float b, uint32_t& hi, uint32_t& lo) {
  __half2 h = __floats2half2_rn(a, b);
  float2 hf = __half22float2(h);
  __half2 l = __floats2half2_rn(a - hf.x, b - hf.y);
  hi = *reinterpret_cast<uint32_t*>(&h);
  lo = *reinterpret_cast<uint32_t*>(&l);
}

// JAX threefry2x32-20, key (0,42), partitionable: counter (0,i), bits=x0^x1
__device__ __forceinline__ unsigned keep_mask(unsigned idx) {
  const unsigned ks1 = 42u, ks2 = 0x1BD11BDAu ^ 42u;
  unsigned x0 = 0u, x1 = idx + ks1;
#define TFR(r) { x0 += x1; x1 = __funnelshift_l(x1, x1, (r)); x1 ^= x0; }
  TFR(13) TFR(15) TFR(26) TFR(6)
  x0 += ks1; x1 += ks2 + 1u;
  TFR(17) TFR(29) TFR(16) TFR(24)
  x0 += ks2; x1 += 2u;
  TFR(13) TFR(15) TFR(26) TFR(6)
  x1 += ks1 + 3u;
  TFR(17) TFR(29) TFR(16) TFR(24)
  x0 += ks1; x1 += ks2 + 4u;
  TFR(13) TFR(15) TFR(26) TFR(6)
  x0 += ks2; x1 += 5u;
#undef TFR
  return ((x0 ^ x1) >> 9) < 7549747u;
}

__global__ void __launch_bounds__(TB, 1)
Model_56358560858161_kernel(const float* __restrict__ Qg, const float* __restrict__ Kg,
                            const float* __restrict__ Vg, float* __restrict__ Og)
{
  extern __shared__ __align__(1024) char smem[];
  const uint32_t sb = (uint32_t)__cvta_generic_to_shared(smem);
  float* REDA = reinterpret_cast<float*>(smem + SM_REDA);
  float* REDB = reinterpret_cast<float*>(smem + SM_REDB);

  const int tid  = threadIdx.x;
  const int lane = tid & 31, w = tid >> 5;
  const int wr = w & 3, wc = w >> 2;           // 4x4 warp grid
  const int b  = blockIdx.x >> 5;
  const int q0 = (blockIdx.x & 31) * BQ;

  const float* Qb = Qg + (size_t)b * NQ * HD;
  const float* Kb = Kg + (size_t)b * NKV * HD;
  const float* Vb = Vg + (size_t)b * NKV * HD;
  const unsigned gbase = (unsigned)(b * NQ + q0);

  // ---- Q -> Qh/Ql f16 (scaled by sqrt(128)), once --------------------------
  {
    const float SC = 11.3137084989847603904f;
    int qr = tid >> 2, cb = (tid & 3) * 32;
    const float* src = Qb + (size_t)(q0 + qr) * HD + cb;
    uint32_t hbase = sb + SM_QH + qr * (QP * 2) + cb * 2;
    uint32_t lbase = sb + SM_QL + qr * (QP * 2) + cb * 2;
    #pragma unroll
    for (int c4 = 0; c4 < 2; ++c4) {           // 2 x 16 cols
      uint32_t hi[8], lo[8];
      #pragma unroll
      for (int j = 0; j < 4; ++j) {
        float4 v = *reinterpret_cast<const float4*>(src + c4 * 16 + 4 * j);
        splith(v.x * SC, v.y * SC, hi[2*j],   lo[2*j]);
        splith(v.z * SC, v.w * SC, hi[2*j+1], lo[2*j+1]);
      }
      sts128(hbase + c4 * 32,      hi[0], hi[1], hi[2], hi[3]);
      sts128(hbase + c4 * 32 + 16, hi[4], hi[5], hi[6], hi[7]);
      sts128(lbase + c4 * 32,      lo[0], lo[1], lo[2], lo[3]);
      sts128(lbase + c4 * 32 + 16, lo[4], lo[5], lo[6], lo[7]);
    }
  }

  float m_[2][2], l_[2][2], OA[2][4][4];
  #pragma unroll
  for (int mt = 0; mt < 2; ++mt)
    #pragma unroll
    for (int h2 = 0; h2 < 2; ++h2) { m_[mt][h2] = -1e30f; l_[mt][h2] = 0.f; }
  #pragma unroll
  for (int mt = 0; mt < 2; ++mt)
    #pragma unroll
    for (int nt = 0; nt < 4; ++nt)
      #pragma unroll
      for (int e = 0; e < 4; ++e) OA[mt][nt][e] = 0.f;

  for (int jt = 0; jt < NT; ++jt) {
    const int j0 = jt * BKV;
    __syncthreads();   // previous tile's consumers done with K/V/P smem

    // ---- K tile -> Kh/Kl [64][KP] ----------------------------------------
    {
      int rr = tid >> 3, cb = (tid & 7) * 16;
      const float* src = Kb + (size_t)(j0 + rr) * HD + cb;
      float4 f0 = *reinterpret_cast<const float4*>(src);
      float4 f1 = *reinterpret_cast<const float4*>(src + 4);
      float4 f2 = *reinterpret_cast<const float4*>(src + 8);
      float4 f3 = *reinterpret_cast<const float4*>(src + 12);
      uint32_t hi[8], lo[8];
      splith(f0.x, f0.y, hi[0], lo[0]); splith(f0.z, f0.w, hi[1], lo[1]);
      splith(f1.x, f1.y, hi[2], lo[2]); splith(f1.z, f1.w, hi[3], lo[3]);
      splith(f2.x, f2.y, hi[4], lo[4]); splith(f2.z, f2.w, hi[5], lo[5]);
      splith(f3.x, f3.y, hi[6], lo[6]); splith(f3.z, f3.w, hi[7], lo[7]);
      uint32_t hb = sb + SM_KH + rr * (KP * 2) + cb * 2;
      uint32_t lb = sb + SM_KL + rr * (KP * 2) + cb * 2;
      sts128(hb,      hi[0], hi[1], hi[2], hi[3]);
      sts128(hb + 16, hi[4], hi[5], hi[6], hi[7]);
      sts128(lb,      lo[0], lo[1], lo[2], lo[3]);
      sts128(lb + 16, lo[4], lo[5], lo[6], lo[7]);
    }
    // ---- V tile -> VTh/VTl transposed [128 h][VP kv] ----------------------
    {
      int p2 = tid >> 4;                 // kv pair 0..31
      int hb = tid & 15;                 // h = hb + 16j
      const float* v0 = Vb + (size_t)(j0 + 2 * p2) * HD;
      const float* v1 = v0 + HD;
      #pragma unroll
      for (int j = 0; j < 8; ++j) {
        int h = hb + 16 * j;
        uint32_t hi, lo;
        splith(v0[h], v1[h], hi, lo);
        sts32(sb + SM_VTH + h * (VP * 2) + p2 * 4, hi);
        sts32(sb + SM_VTL + h * (VP * 2) + p2 * 4, lo);
      }
    }
    __syncthreads();

    // ---- S = Q K^T: warp block rows 32wr..+31, cols 16wc..+15 -------------
    float acc[2][2][4];
    #pragma unroll
    for (int mt = 0; mt < 2; ++mt)
      #pragma unroll
      for (int nt = 0; nt < 2; ++nt)
        #pragma unroll
        for (int e = 0; e < 4; ++e) acc[mt][nt][e] = 0.f;

    #pragma unroll
    for (int ks = 0; ks < 8; ++ks) {
      int k0 = ks * 16;
      uint32_t ah0[4], ah1[4], al0[4], al1[4], bh[4], bl[4];
      ldsm4(ah0, tadr(sb + SM_QH, QP * 2, 32 * wr,      k0, lane));
      ldsm4(ah1, tadr(sb + SM_QH, QP * 2, 32 * wr + 16, k0, lane));
      ldsm4(al0, tadr(sb + SM_QL, QP * 2, 32 * wr,      k0, lane));
      ldsm4(al1, tadr(sb + SM_QL, QP * 2, 32 * wr + 16, k0, lane));
      ldsm4(bh,  tadr(sb + SM_KH, KP * 2, 16 * wc,      k0, lane));
      ldsm4(bl,  tadr(sb + SM_KL, KP * 2, 16 * wc,      k0, lane));
      mma_(acc[0][0], ah0, bh[0], bh[2]); mma_(acc[0][1], ah0, bh[1], bh[3]);
      mma_(acc[1][0], ah1, bh[0], bh[2]); mma_(acc[1][1], ah1, bh[1], bh[3]);
      mma_(acc[0][0], ah0, bl[0], bl[2]); mma_(acc[0][1], ah0, bl[1], bl[3]);
      mma_(acc[1][0], ah1, bl[0], bl[2]); mma_(acc[1][1], ah1, bl[1], bl[3]);
      mma_(acc[0][0], al0, bh[0], bh[2]); mma_(acc[0][1], al0, bh[1], bh[3]);
      mma_(acc[1][0], al1, bh[0], bh[2]); mma_(acc[1][1], al1, bh[1], bh[3]);
    }

    // ---- online softmax ---------------------------------------------------
    // thread rows: 32wr + 16mt + 8h2 + lane/4 ; cols: 16wc + 2(lane&3)+{0,1}, +8
    float mnew[2][2], corr[2][2];
    #pragma unroll
    for (int mt = 0; mt < 2; ++mt)
      #pragma unroll
      for (int h2 = 0; h2 < 2; ++h2) {
        float v0 = acc[mt][0][2*h2], v1 = acc[mt][0][2*h2+1];
        float v2 = acc[mt][1][2*h2], v3 = acc[mt][1][2*h2+1];
        float mx = fmaxf(fmaxf(v0, v1), fmaxf(v2, v3));
        mx = fmaxf(mx, __shfl_xor_sync(0xffffffffu, mx, 1));
        mx = fmaxf(mx, __shfl_xor_sync(0xffffffffu, mx, 2));
        if ((lane & 3) == 0) {
          int row = 32 * wr + 16 * mt + 8 * h2 + (lane >> 2);
          REDA[wc * 128 + row] = mx;
        }
      }
    __syncthreads();
    #pragma unroll
    for (int mt = 0; mt < 2; ++mt)
      #pragma unroll
      for (int h2 = 0; h2 < 2; ++h2) {
        int row = 32 * wr + 16 * mt + 8 * h2 + (lane >> 2);
        float mx = m_[mt][h2];
        #pragma unroll
        for (int w2 = 0; w2 < 4; ++w2) mx = fmaxf(mx, REDA[w2 * 128 + row]);
        corr[mt][h2] = __expf(m_[mt][h2] - mx);
        mnew[mt][h2] = mx;
        float s = 0.f;
        #pragma unroll
        for (int nt = 0; nt < 2; ++nt)
          #pragma unroll
          for (int e = 0; e < 2; ++e) {
            float ex = __expf(acc[mt][nt][2*h2+e] - mx);
            acc[mt][nt][2*h2+e] = ex;
            s += ex;
          }
        s += __shfl_xor_sync(0xffffffffu, s, 1);
        s += __shfl_xor_sync(0xffffffffu, s, 2);
        if ((lane & 3) == 0) REDB[wc * 128 + row] = s;
      }
    __syncthreads();
    #pragma unroll
    for (int mt = 0; mt < 2; ++mt)
      #pragma unroll
      for (int h2 = 0; h2 < 2; ++h2) {
        int row = 32 * wr + 16 * mt + 8 * h2 + (lane >> 2);
        float rs = 0.f;
        #pragma unroll
        for (int w2 = 0; w2 < 4; ++w2) rs += REDB[w2 * 128 + row];
        l_[mt][h2] = l_[mt][h2] * corr[mt][h2] + rs;
        m_[mt][h2] = mnew[mt][h2];
      }

    // ---- dropout + P -> Ph/Pl f16 ----------------------------------------
    #pragma unroll
    for (int mt = 0; mt < 2; ++mt)
      #pragma unroll
      for (int h2 = 0; h2 < 2; ++h2) {
        int row = 32 * wr + 16 * mt + 8 * h2 + (lane >> 2);
        unsigned ib = (gbase + (unsigned)row) * (unsigned)NKV
                    + (unsigned)(j0 + 16 * wc + 2 * (lane & 3));
        float e0 = keep_mask(ib)      ? acc[mt][0][2*h2]   : 0.f;
        float e1 = keep_mask(ib + 1u) ? acc[mt][0][2*h2+1] : 0.f;
        float e2 = keep_mask(ib + 8u) ? acc[mt][1][2*h2]   : 0.f;
        float e3 = keep_mask(ib + 9u) ? acc[mt][1][2*h2+1] : 0.f;
        uint32_t h01, l01, h23, l23;
        splith(e0, e1, h01, l01);
        splith(e2, e3, h23, l23);
        uint32_t off = row * (PP * 2) + (16 * wc + 2 * (lane & 3)) * 2;
        sts32(sb + SM_PH + off,      h01);
        sts32(sb + SM_PH + off + 16, h23);
        sts32(sb + SM_PL + off,      l01);
        sts32(sb + SM_PL + off + 16, l23);
      }
    __syncthreads();

    // ---- O = O*corr + P V: warp block rows 32wr..+31, cols 32wc..+31 -----
    #pragma unroll
    for (int mt = 0; mt < 2; ++mt)
      #pragma unroll
      for (int nt = 0; nt < 4; ++nt)
        #pragma unroll
        for (int e = 0; e < 4; ++e) OA[mt][nt][e] *= corr[mt][e >> 1];

    #pragma unroll
    for (int ks = 0; ks < 4; ++ks) {
      int k0 = ks * 16;
      uint32_t ph0[4], ph1[4], pl0[4], pl1[4];
      uint32_t vhA[4], vhB[4], vlA[4], vlB[4];
      ldsm4(ph0, tadr(sb + SM_PH,  PP * 2, 32 * wr,      k0, lane));
      ldsm4(ph1, tadr(sb + SM_PH,  PP * 2, 32 * wr + 16, k0, lane));
      ldsm4(pl0, tadr(sb + SM_PL,  PP * 2, 32 * wr,      k0, lane));
      ldsm4(pl1, tadr(sb + SM_PL,  PP * 2, 32 * wr + 16, k0, lane));
      ldsm4(vhA, tadr(sb + SM_VTH, VP * 2, 32 * wc,      k0, lane));
      ldsm4(vhB, tadr(sb + SM_VTH, VP * 2, 32 * wc + 16, k0, lane));
      ldsm4(vlA, tadr(sb + SM_VTL, VP * 2, 32 * wc,      k0, lane));
      ldsm4(vlB, tadr(sb + SM_VTL, VP * 2, 32 * wc + 16, k0, lane));
      // n-tiles: 0:{vA0,vA2} 1:{vA1,vA3} 2:{vB0,vB2} 3:{vB1,vB3}
      mma_(OA[0][0], ph0, vhA[0], vhA[2]); mma_(OA[0][1], ph0, vhA[1], vhA[3]);
      mma_(OA[0][2], ph0, vhB[0], vhB[2]); mma_(OA[0][3], ph0, vhB[1], vhB[3]);
      mma_(OA[1][0], ph1, vhA[0], vhA[2]); mma_(OA[1][1], ph1, vhA[1], vhA[3]);
      mma_(OA[1][2], ph1, vhB[0], vhB[2]); mma_(OA[1][3], ph1, vhB[1], vhB[3]);
      mma_(OA[0][0], ph0, vlA[0], vlA[2]); mma_(OA[0][1], ph0, vlA[1], vlA[3]);
      mma_(OA[0][2], ph0, vlB[0], vlB[2]); mma_(OA[0][3], ph0, vlB[1], vlB[3]);
      mma_(OA[1][0], ph1, vlA[0], vlA[2]); mma_(OA[1][1], ph1, vlA[1], vlA[3]);
      mma_(OA[1][2], ph1, vlB[0], vlB[2]); mma_(OA[1][3], ph1, vlB[1], vlB[3]);
      mma_(OA[0][0], pl0, vhA[0], vhA[2]); mma_(OA[0][1], pl0, vhA[1], vhA[3]);
      mma_(OA[0][2], pl0, vhB[0], vhB[2]); mma_(OA[0][3], pl0, vhB[1], vhB[3]);
      mma_(OA[1][0], pl1, vhA[0], vhA[2]); mma_(OA[1][1], pl1, vhA[1], vhA[3]);
      mma_(OA[1][2], pl1, vhB[0], vhB[2]); mma_(OA[1][3], pl1, vhB[1], vhB[3]);
    }
  }

  // ---- epilogue: /(l * 0.9) -----------------------------------------------
  #pragma unroll
  for (int mt = 0; mt < 2; ++mt) {
    float inv0 = 1.0f / (l_[mt][0] * 0.9f);
    float inv1 = 1.0f / (l_[mt][1] * 0.9f);
    #pragma unroll
    for (int nt = 0; nt < 4; ++nt) {
      int col = 32 * wc + 8 * nt + 2 * (lane & 3);
      #pragma unroll
      for (int h2 = 0; h2 < 2; ++h2) {
        int row = 32 * wr + 16 * mt + 8 * h2 + (lane >> 2);
        float inv = h2 ? inv1 : inv0;
        float2 o;
        o.x = OA[mt][nt][2*h2]   * inv;
        o.y = OA[mt][nt][2*h2+1] * inv;
        *reinterpret_cast<float2*>(Og + (size_t)(gbase + row) * HD + col) = o;
      }
    }
  }
}

extern "C" void kernel_launch(void* const* d_in, const int* in_sizes, int n_in,
                              void* d_out, int out_size) {
  const float* Q = (const float*)d_in[0];
  const float* K = (const float*)d_in[1];
  const float* V = (const float*)d_in[2];
  float* O = (float*)d_out;
  (void)in_sizes; (void)n_in; (void)out_size;
  cudaFuncSetAttribute(Model_56358560858161_kernel,
                       cudaFuncAttributeMaxDynamicSharedMemorySize, (int)SM_TOT);
  Model_56358560858161_kernel<<<128, TB, SM_TOT>>>(Q, K, V, O);
}

// round 8
// speedup vs baseline: 2.4738x; 1.1368x over previous
#include <cuda_runtime.h>
#include <cuda_fp16.h>
#include <cstdint>

// HMMA flash-attention, 3-term fp16 split on S, 2-term on AV, exact JAX
// threefry dropout, cp.async-prefetched raw K/V, single-sync softmax reduce.
// B=4, Q=4096, NKV=4096, H=128, scale=+sqrt(128) folded into Q.
// 128 CTAs x 512 threads (16 warps, 4x4 grid).

#define TB  512
#define BQ  128
#define BKV 64
#define HD  128
#define NQ  4096
#define NKV 4096
#define NT  (NKV/BKV)

#define QP 136
#define KP 136
#define VP 72
#define PP 72

#define SM_QH   0u
#define SM_QL   34816u
#define SM_KH   69632u
#define SM_KL   87040u
#define SM_VTH  104448u
#define SM_VTL  122880u
#define SM_PH   141312u
#define SM_RED  159744u
#define SM_RAWK 163840u
#define SM_RAWV 196608u
#define SM_TOT  229376u

__device__ __forceinline__ void ldsm4(uint32_t* r, uint32_t a) {
  asm volatile("ldmatrix.sync.aligned.m8n8.x4.shared.b16 {%0,%1,%2,%3},[%4];"
               : "=r"(r[0]), "=r"(r[1]), "=r"(r[2]), "=r"(r[3]) : "r"(a));
}
__device__ __forceinline__ uint32_t tadr(uint32_t base, int pitchB, int r0, int c0, int lane) {
  int rr = r0 + (lane & 7) + ((lane >> 3) & 1) * 8;
  int cc = c0 + (lane >> 4) * 8;
  return base + rr * pitchB + cc * 2;
}
__device__ __forceinline__ void mma_(float* d, const uint32_t* a, uint32_t b0, uint32_t b1) {
  asm volatile(
    "mma.sync.aligned.m16n8k16.row.col.f32.f16.f16.f32 "
    "{%0,%1,%2,%3},{%4,%5,%6,%7},{%8,%9},{%0,%1,%2,%3};"
    : "+f"(d[0]), "+f"(d[1]), "+f"(d[2]), "+f"(d[3])
    : "r"(a[0]), "r"(a[1]), "r"(a[2]), "r"(a[3]), "r"(b0), "r"(b1));
}
__device__ __forceinline__ void sts128(uint32_t a, uint32_t x, uint32_t y, uint32_t z, uint32_t w) {
  asm volatile("st.shared.v4.b32 [%0],{%1,%2,%3,%4};" :: "r"(a), "r"(x), "r"(y), "r"(z), "r"(w));
}
__device__ __forceinline__ void sts64(uint32_t a, uint32_t x, uint32_t y) {
  asm volatile("st.shared.v2.b32 [%0],{%1,%2};" :: "r"(a), "r"(x), "r"(y));
}
__device__ __forceinline__ void sts32(uint32_t a, uint32_t x) {
  asm volatile("st.shared.b32 [%0],%1;" :: "r"(a), "r"(x));
}
__device__ __forceinline__ void cpa16(uint32_t d, const float* s) {
  asm volatile("cp.async.cg.shared.global [%0],[%1],16;" :: "r"(d), "l"(s));
}
__device__ __forceinline__ void cpa_commit() { asm volatile("cp.async.commit_group;"); }
__device__ __forceinline__ void cpa_wait()   { asm volatile("cp.async.wait_group 0;"); }

__device__ __forceinline__ void splith(float a, float b, uint32_t& hi, uint32_t& lo) {
  __half2 h = __floats2half2_rn(a, b);
  float2 hf = __half22float2(h);
  __half2 l = __floats2half2_rn(a - hf.x, b - hf.y);
  hi = *reinterpret_cast<uint32_t*>(&h);
  lo = *reinterpret_cast<uint32_t*>(&l);
}
__device__ __forceinline__ uint32_t packh(float a, float b) {
  __half2 h = __floats2half2_rn(a, b);
  return *reinterpret_cast<uint32_t*>(&h);
}

// JAX threefry2x32-20, key (0,42), partitionable: counter (0,i), bits=x0^x1
__device__ __forceinline__ unsigned keep_mask(unsigned idx) {
  const unsigned ks1 = 42u, ks2 = 0x1BD11BDAu ^ 42u;
  unsigned x0 = 0u, x1 = idx + ks1;
#define TFR(r) { x0 += x1; x1 = __funnelshift_l(x1, x1, (r)); x1 ^= x0; }
  TFR(13) TFR(15) TFR(26) TFR(6)
  x0 += ks1; x1 += ks2 + 1u;
  TFR(17) TFR(29) TFR(16) TFR(24)
  x0 += ks2; x1 += 2u;
  TFR(13) TFR(15) TFR(26) TFR(6)
  x1 += ks1 + 3u;
  TFR(17) TFR(29) TFR(16) TFR(24)
  x0 += ks1; x1 += ks2 + 4u;
  TFR(13) TFR(15) TFR(26) TFR(6)
  x0 += ks2; x1 += 5u;
#undef TFR
  return ((x0 ^ x1) >> 9) < 7549747u;
}

__global__ void __launch_bounds__(TB, 1)
Model_56358560858161_kernel(const float* __restrict__ Qg, const float* __restrict__ Kg,
                            const float* __restrict__ Vg, float* __restrict__ Og)
{
  extern __shared__ __align__(1024) char smem[];
  const uint32_t sb = (uint32_t)__cvta_generic_to_shared(smem);
  float2* RED = reinterpret_cast<float2*>(smem + SM_RED);   // [4][128] (mw, sw)
  const float* rawK = reinterpret_cast<const float*>(smem + SM_RAWK);
  const float* rawV = reinterpret_cast<const float*>(smem + SM_RAWV);

  const int tid  = threadIdx.x;
  const int lane = tid & 31, w = tid >> 5;
  const int wr = w & 3, wc = w >> 2;
  const int b  = blockIdx.x >> 5;
  const int q0 = (blockIdx.x & 31) * BQ;

  const float* Qb = Qg + (size_t)b * NQ * HD;
  const float* Kb = Kg + (size_t)b * NKV * HD;
  const float* Vb = Vg + (size_t)b * NKV * HD;
  const unsigned gbase = (unsigned)(b * NQ + q0);

  // ---- prefetch raw K/V tile 0 ---------------------------------------------
  #pragma unroll
  for (int it = 0; it < 4; ++it) {
    int c = tid + it * TB;
    cpa16(sb + SM_RAWK + c * 16, Kb + c * 4);
    cpa16(sb + SM_RAWV + c * 16, Vb + c * 4);
  }
  cpa_commit();

  // ---- Q -> Qh/Ql f16 (scaled), once ---------------------------------------
  {
    const float SC = 11.3137084989847603904f;
    int qr = tid >> 2, cb = (tid & 3) * 32;
    const float* src = Qb + (size_t)(q0 + qr) * HD + cb;
    uint32_t hbase = sb + SM_QH + qr * (QP * 2) + cb * 2;
    uint32_t lbase = sb + SM_QL + qr * (QP * 2) + cb * 2;
    #pragma unroll
    for (int c4 = 0; c4 < 2; ++c4) {
      uint32_t hi[8], lo[8];
      #pragma unroll
      for (int j = 0; j < 4; ++j) {
        float4 v = *reinterpret_cast<const float4*>(src + c4 * 16 + 4 * j);
        splith(v.x * SC, v.y * SC, hi[2*j],   lo[2*j]);
        splith(v.z * SC, v.w * SC, hi[2*j+1], lo[2*j+1]);
      }
      sts128(hbase + c4 * 32,      hi[0], hi[1], hi[2], hi[3]);
      sts128(hbase + c4 * 32 + 16, hi[4], hi[5], hi[6], hi[7]);
      sts128(lbase + c4 * 32,      lo[0], lo[1], lo[2], lo[3]);
      sts128(lbase + c4 * 32 + 16, lo[4], lo[5], lo[6], lo[7]);
    }
  }

  float m_[2][2], l_[2][2], OA[2][4][4];
  #pragma unroll
  for (int mt = 0; mt < 2; ++mt)
    #pragma unroll
    for (int h2 = 0; h2 < 2; ++h2) { m_[mt][h2] = -1e30f; l_[mt][h2] = 0.f; }
  #pragma unroll
  for (int mt = 0; mt < 2; ++mt)
    #pragma unroll
    for (int nt = 0; nt < 4; ++nt)
      #pragma unroll
      for (int e = 0; e < 4; ++e) OA[mt][nt][e] = 0.f;

  for (int jt = 0; jt < NT; ++jt) {
    const int j0 = jt * BKV;
    cpa_wait();
    __syncthreads();   // raw(jt) arrived; all warps done with prev tile MMAs

    // ---- K raw -> Kh/Kl (conflict-free float4 reads) -----------------------
    #pragma unroll
    for (int it = 0; it < 4; ++it) {
      int c = tid + it * TB;
      int row = c >> 5, c4 = (c & 31) * 4;
      float4 v = *reinterpret_cast<const float4*>(rawK + c * 4);
      uint32_t h0, l0, h1, l1;
      splith(v.x, v.y, h0, l0);
      splith(v.z, v.w, h1, l1);
      sts64(sb + SM_KH + row * (KP * 2) + c4 * 2, h0, h1);
      sts64(sb + SM_KL + row * (KP * 2) + c4 * 2, l0, l1);
    }
    // ---- V raw -> VTh/VTl transposed ---------------------------------------
    {
      int p2 = tid >> 4, hb = tid & 15;
      const float* r0 = rawV + (2 * p2) * HD;
      const float* r1 = r0 + HD;
      #pragma unroll
      for (int j = 0; j < 8; ++j) {
        int h = hb + 16 * j;
        uint32_t hi, lo;
        splith(r0[h], r1[h], hi, lo);
        sts32(sb + SM_VTH + h * (VP * 2) + p2 * 4, hi);
        sts32(sb + SM_VTL + h * (VP * 2) + p2 * 4, lo);
      }
    }
    __syncthreads();   // conv visible; raw reads done -> safe to overwrite raw

    // ---- prefetch raw(jt+1) (hidden under MMAs/softmax) --------------------
    if (jt + 1 < NT) {
      const float* kn = Kb + (size_t)(j0 + BKV) * HD;
      const float* vn = Vb + (size_t)(j0 + BKV) * HD;
      #pragma unroll
      for (int it = 0; it < 4; ++it) {
        int c = tid + it * TB;
        cpa16(sb + SM_RAWK + c * 16, kn + c * 4);
        cpa16(sb + SM_RAWV + c * 16, vn + c * 4);
      }
    }
    cpa_commit();

    // ---- S = Q K^T ---------------------------------------------------------
    float acc[2][2][4];
    #pragma unroll
    for (int mt = 0; mt < 2; ++mt)
      #pragma unroll
      for (int nt = 0; nt < 2; ++nt)
        #pragma unroll
        for (int e = 0; e < 4; ++e) acc[mt][nt][e] = 0.f;

    #pragma unroll
    for (int ks = 0; ks < 8; ++ks) {
      int k0 = ks * 16;
      uint32_t ah0[4], ah1[4], al0[4], al1[4], bh[4], bl[4];
      ldsm4(ah0, tadr(sb + SM_QH, QP * 2, 32 * wr,      k0, lane));
      ldsm4(ah1, tadr(sb + SM_QH, QP * 2, 32 * wr + 16, k0, lane));
      ldsm4(al0, tadr(sb + SM_QL, QP * 2, 32 * wr,      k0, lane));
      ldsm4(al1, tadr(sb + SM_QL, QP * 2, 32 * wr + 16, k0, lane));
      ldsm4(bh,  tadr(sb + SM_KH, KP * 2, 16 * wc,      k0, lane));
      ldsm4(bl,  tadr(sb + SM_KL, KP * 2, 16 * wc,      k0, lane));
      mma_(acc[0][0], ah0, bh[0], bh[2]); mma_(acc[0][1], ah0, bh[1], bh[3]);
      mma_(acc[1][0], ah1, bh[0], bh[2]); mma_(acc[1][1], ah1, bh[1], bh[3]);
      mma_(acc[0][0], ah0, bl[0], bl[2]); mma_(acc[0][1], ah0, bl[1], bl[3]);
      mma_(acc[1][0], ah1, bl[0], bl[2]); mma_(acc[1][1], ah1, bl[1], bl[3]);
      mma_(acc[0][0], al0, bh[0], bh[2]); mma_(acc[0][1], al0, bh[1], bh[3]);
      mma_(acc[1][0], al1, bh[0], bh[2]); mma_(acc[1][1], al1, bh[1], bh[3]);
    }

    // ---- softmax: warp-local (mw, sw), ONE sync ----------------------------
    float mw[2][2];
    #pragma unroll
    for (int mt = 0; mt < 2; ++mt)
      #pragma unroll
      for (int h2 = 0; h2 < 2; ++h2) {
        float v0 = acc[mt][0][2*h2], v1 = acc[mt][0][2*h2+1];
        float v2 = acc[mt][1][2*h2], v3 = acc[mt][1][2*h2+1];
        float mx = fmaxf(fmaxf(v0, v1), fmaxf(v2, v3));
        mx = fmaxf(mx, __shfl_xor_sync(0xffffffffu, mx, 1));
        mx = fmaxf(mx, __shfl_xor_sync(0xffffffffu, mx, 2));
        mw[mt][h2] = mx;
        float s = 0.f;
        #pragma unroll
        for (int nt = 0; nt < 2; ++nt)
          #pragma unroll
          for (int e = 0; e < 2; ++e) {
            float ex = __expf(acc[mt][nt][2*h2+e] - mx);
            acc[mt][nt][2*h2+e] = ex;
            s += ex;
          }
        s += __shfl_xor_sync(0xffffffffu, s, 1);
        s += __shfl_xor_sync(0xffffffffu, s, 2);
        if ((lane & 3) == 0) {
          int row = 32 * wr + 16 * mt + 8 * h2 + (lane >> 2);
          RED[wc * 128 + row] = make_float2(mx, s);
        }
      }
    __syncthreads();

    float corr[2][2], f_[2][2];
    #pragma unroll
    for (int mt = 0; mt < 2; ++mt)
      #pragma unroll
      for (int h2 = 0; h2 < 2; ++h2) {
        int row = 32 * wr + 16 * mt + 8 * h2 + (lane >> 2);
        float2 rw[4];
        #pragma unroll
        for (int w2 = 0; w2 < 4; ++w2) rw[w2] = RED[w2 * 128 + row];
        float mnew = m_[mt][h2];
        #pragma unroll
        for (int w2 = 0; w2 < 4; ++w2) mnew = fmaxf(mnew, rw[w2].x);
        float c_ = __expf(m_[mt][h2] - mnew);
        float ls = l_[mt][h2] * c_;
        #pragma unroll
        for (int w2 = 0; w2 < 4; ++w2) ls += rw[w2].y * __expf(rw[w2].x - mnew);
        corr[mt][h2] = c_;
        f_[mt][h2]   = __expf(mw[mt][h2] - mnew);
        l_[mt][h2] = ls;
        m_[mt][h2] = mnew;
      }

    // ---- dropout + P (hi only) -> smem -------------------------------------
    #pragma unroll
    for (int mt = 0; mt < 2; ++mt)
      #pragma unroll
      for (int h2 = 0; h2 < 2; ++h2) {
        int row = 32 * wr + 16 * mt + 8 * h2 + (lane >> 2);
        float fr = f_[mt][h2];
        unsigned ib = (gbase + (unsigned)row) * (unsigned)NKV
                    + (unsigned)(j0 + 16 * wc + 2 * (lane & 3));
        float e0 = keep_mask(ib)      ? acc[mt][0][2*h2]   * fr : 0.f;
        float e1 = keep_mask(ib + 1u) ? acc[mt][0][2*h2+1] * fr : 0.f;
        float e2 = keep_mask(ib + 8u) ? acc[mt][1][2*h2]   * fr : 0.f;
        float e3 = keep_mask(ib + 9u) ? acc[mt][1][2*h2+1] * fr : 0.f;
        uint32_t off = row * (PP * 2) + (16 * wc + 2 * (lane & 3)) * 2;
        sts32(sb + SM_PH + off,      packh(e0, e1));
        sts32(sb + SM_PH + off + 16, packh(e2, e3));
      }
    __syncthreads();

    // ---- O = O*corr + P V (2-term) -----------------------------------------
    #pragma unroll
    for (int mt = 0; mt < 2; ++mt)
      #pragma unroll
      for (int nt = 0; nt < 4; ++nt)
        #pragma unroll
        for (int e = 0; e < 4; ++e) OA[mt][nt][e] *= corr[mt][e >> 1];

    #pragma unroll
    for (int ks = 0; ks < 4; ++ks) {
      int k0 = ks * 16;
      uint32_t ph0[4], ph1[4], vhA[4], vhB[4], vlA[4], vlB[4];
      ldsm4(ph0, tadr(sb + SM_PH,  PP * 2, 32 * wr,      k0, lane));
      ldsm4(ph1, tadr(sb + SM_PH,  PP * 2, 32 * wr + 16, k0, lane));
      ldsm4(vhA, tadr(sb + SM_VTH, VP * 2, 32 * wc,      k0, lane));
      ldsm4(vhB, tadr(sb + SM_VTH, VP * 2, 32 * wc + 16, k0, lane));
      ldsm4(vlA, tadr(sb + SM_VTL, VP * 2, 32 * wc,      k0, lane));
      ldsm4(vlB, tadr(sb + SM_VTL, VP * 2, 32 * wc + 16, k0, lane));
      mma_(OA[0][0], ph0, vhA[0], vhA[2]); mma_(OA[0][1], ph0, vhA[1], vhA[3]);
      mma_(OA[0][2], ph0, vhB[0], vhB[2]); mma_(OA[0][3], ph0, vhB[1], vhB[3]);
      mma_(OA[1][0], ph1, vhA[0], vhA[2]); mma_(OA[1][1], ph1, vhA[1], vhA[3]);
      mma_(OA[1][2], ph1, vhB[0], vhB[2]); mma_(OA[1][3], ph1, vhB[1], vhB[3]);
      mma_(OA[0][0], ph0, vlA[0], vlA[2]); mma_(OA[0][1], ph0, vlA[1], vlA[3]);
      mma_(OA[0][2], ph0, vlB[0], vlB[2]); mma_(OA[0][3], ph0, vlB[1], vlB[3]);
      mma_(OA[1][0], ph1, vlA[0], vlA[2]); mma_(OA[1][1], ph1, vlA[1], vlA[3]);
      mma_(OA[1][2], ph1, vlB[0], vlB[2]); mma_(OA[1][3], ph1, vlB[1], vlB[3]);
    }
  }

  // ---- epilogue ------------------------------------------------------------
  #pragma unroll
  for (int mt = 0; mt < 2; ++mt) {
    float inv0 = 1.0f / (l_[mt][0] * 0.9f);
    float inv1 = 1.0f / (l_[mt][1] * 0.9f);
    #pragma unroll
    for (int nt = 0; nt < 4; ++nt) {
      int col = 32 * wc + 8 * nt + 2 * (lane & 3);
      #pragma unroll
      for (int h2 = 0; h2 < 2; ++h2) {
        int row = 32 * wr + 16 * mt + 8 * h2 + (lane >> 2);
        float inv = h2 ? inv1 : inv0;
        float2 o;
        o.x = OA[mt][nt][2*h2]   * inv;
        o.y = OA[mt][nt][2*h2+1] * inv;
        *reinterpret_cast<float2*>(Og + (size_t)(gbase + row) * HD + col) = o;
      }
    }
  }
}

extern "C" void kernel_launch(void* const* d_in, const int* in_sizes, int n_in,
                              void* d_out, int out_size) {
  const float* Q = (const float*)d_in[0];
  const float* K = (const float*)d_in[1];
  const float* V = (const float*)d_in[2];
  float* O = (float*)d_out;
  (void)in_sizes; (void)n_in; (void)out_size;
  cudaFuncSetAttribute(Model_56358560858161_kernel,
                       cudaFuncAttributeMaxDynamicSharedMemorySize, (int)SM_TOT);
  Model_56358560858161_kernel<<<128, TB, SM_TOT>>>(Q, K, V, O);
}

// round 9
// speedup vs baseline: 2.4817x; 1.0032x over previous
#include <cuda_runtime.h>
#include <cuda_fp16.h>
#include <cstdint>

// HMMA flash-attention, 3-term fp16 split S / 2-term AV, exact JAX threefry
// dropout. Round 9: BQ=64 / 256-thread CTAs / 256 CTAs -> 2 CTAs per SM,
// swizzled unpadded smem (106 KB), direct LDG conversions, ldmatrix.trans
// for V (no explicit transpose).
// B=4, Q=4096, NKV=4096, H=128, scale=+sqrt(128) folded into Q.

#define TB  256
#define BQ  64
#define BKV 64
#define HD  128
#define NQ  4096
#define NKV 4096
#define NT  (NKV/BKV)

// smem byte offsets; Q/K/V rows are 256B (128 halves), P rows 128B (64 halves)
#define SM_QH  0u
#define SM_QL  16384u
#define SM_KH  32768u
#define SM_KL  49152u
#define SM_VH  65536u
#define SM_VL  81920u
#define SM_PH  98304u
#define SM_RED 106496u
#define SM_TOT 108544u

// ---- swizzled addressing (16B chunk ^ (row & 7)) ---------------------------
__device__ __forceinline__ uint32_t adr256(uint32_t base, int row, int colB) {
  uint32_t ch = ((uint32_t)colB >> 4) ^ ((uint32_t)row & 7u);
  return base + (uint32_t)row * 256u + ch * 16u + ((uint32_t)colB & 15u);
}
__device__ __forceinline__ uint32_t adr128(uint32_t base, int row, int colB) {
  uint32_t ch = ((uint32_t)colB >> 4) ^ ((uint32_t)row & 7u);
  return base + (uint32_t)row * 128u + ch * 16u + ((uint32_t)colB & 15u);
}
// A/B fragment addr (non-trans): 16x16 tile at (r0, c0 halves)
__device__ __forceinline__ uint32_t tadrA(uint32_t base, int r0, int c0, int lane) {
  int rr = r0 + (lane & 7) + ((lane >> 3) & 1) * 8;
  int cB = (c0 + ((lane >> 4) << 3)) * 2;
  return adr256(base, rr, cB);
}
__device__ __forceinline__ uint32_t tadrP(uint32_t base, int r0, int c0, int lane) {
  int rr = r0 + (lane & 7) + ((lane >> 3) & 1) * 8;
  int cB = (c0 + ((lane >> 4) << 3)) * 2;
  return adr128(base, rr, cB);
}
// V via ldmatrix.trans from row-major V[kv][h]: n0 = h col block, k0 = kv block
__device__ __forceinline__ uint32_t tadrVT(uint32_t base, int n0, int k0, int lane) {
  int rr = k0 + (lane & 7) + (((lane >> 4) & 1) << 3);
  int cB = (n0 + (((lane >> 3) & 1) << 3)) * 2;
  return adr256(base, rr, cB);
}

__device__ __forceinline__ void ldsm4(uint32_t* r, uint32_t a) {
  asm volatile("ldmatrix.sync.aligned.m8n8.x4.shared.b16 {%0,%1,%2,%3},[%4];"
               : "=r"(r[0]), "=r"(r[1]), "=r"(r[2]), "=r"(r[3]) : "r"(a));
}
__device__ __forceinline__ void ldsm4t(uint32_t* r, uint32_t a) {
  asm volatile("ldmatrix.sync.aligned.m8n8.x4.trans.shared.b16 {%0,%1,%2,%3},[%4];"
               : "=r"(r[0]), "=r"(r[1]), "=r"(r[2]), "=r"(r[3]) : "r"(a));
}
__device__ __forceinline__ void mma_(float* d, const uint32_t* a, uint32_t b0, uint32_t b1) {
  asm volatile(
    "mma.sync.aligned.m16n8k16.row.col.f32.f16.f16.f32 "
    "{%0,%1,%2,%3},{%4,%5,%6,%7},{%8,%9},{%0,%1,%2,%3};"
    : "+f"(d[0]), "+f"(d[1]), "+f"(d[2]), "+f"(d[3])
    : "r"(a[0]), "r"(a[1]), "r"(a[2]), "r"(a[3]), "r"(b0), "r"(b1));
}
__device__ __forceinline__ void sts64(uint32_t a, uint32_t x, uint32_t y) {
  asm volatile("st.shared.v2.b32 [%0],{%1,%2};" :: "r"(a), "r"(x), "r"(y));
}
__device__ __forceinline__ void sts32(uint32_t a, uint32_t x) {
  asm volatile("st.shared.b32 [%0],%1;" :: "r"(a), "r"(x));
}
__device__ __forceinline__ void splith(float a, float b, uint32_t& hi, uint32_t& lo) {
  __half2 h = __floats2half2_rn(a, b);
  float2 hf = __half22float2(h);
  __half2 l = __floats2half2_rn(a - hf.x, b - hf.y);
  hi = *reinterpret_cast<uint32_t*>(&h);
  lo = *reinterpret_cast<uint32_t*>(&l);
}
__device__ __forceinline__ uint32_t packh(float a, float b) {
  __half2 h = __floats2half2_rn(a, b);
  return *reinterpret_cast<uint32_t*>(&h);
}

// JAX threefry2x32-20, key (0,42), partitionable: counter (0,i), bits=x0^x1
__device__ __forceinline__ unsigned keep_mask(unsigned idx) {
  const unsigned ks1 = 42u, ks2 = 0x1BD11BDAu ^ 42u;
  unsigned x0 = 0u, x1 = idx + ks1;
#define TFR(r) { x0 += x1; x1 = __funnelshift_l(x1, x1, (r)); x1 ^= x0; }
  TFR(13) TFR(15) TFR(26) TFR(6)
  x0 += ks1; x1 += ks2 + 1u;
  TFR(17) TFR(29) TFR(16) TFR(24)
  x0 += ks2; x1 += 2u;
  TFR(13) TFR(15) TFR(26) TFR(6)
  x1 += ks1 + 3u;
  TFR(17) TFR(29) TFR(16) TFR(24)
  x0 += ks1; x1 += ks2 + 4u;
  TFR(13) TFR(15) TFR(26) TFR(6)
  x0 += ks2; x1 += 5u;
#undef TFR
  return ((x0 ^ x1) >> 9) < 7549747u;
}

__global__ void __launch_bounds__(TB, 2)
Model_56358560858161_kernel(const float* __restrict__ Qg, const float* __restrict__ Kg,
                            const float* __restrict__ Vg, float* __restrict__ Og)
{
  extern __shared__ __align__(1024) char smem[];
  const uint32_t sb = (uint32_t)__cvta_generic_to_shared(smem);
  float2* RED = reinterpret_cast<float2*>(smem + SM_RED);   // [4 wc][64 rows]

  const int tid  = threadIdx.x;
  const int lane = tid & 31, w = tid >> 5;
  const int wr = w & 1, wc = w >> 1;          // 2x4 warp grid
  const int b  = blockIdx.x >> 6;
  const int q0 = (blockIdx.x & 63) * BQ;

  const float* Qb = Qg + (size_t)b * NQ * HD;
  const float* Kb = Kg + (size_t)b * NKV * HD;
  const float* Vb = Vg + (size_t)b * NKV * HD;
  const unsigned gbase = (unsigned)(b * NQ + q0);

  // ---- Q -> Qh/Ql f16 (scaled), once ---------------------------------------
  {
    const float SC = 11.3137084989847603904f;
    #pragma unroll
    for (int it = 0; it < 8; ++it) {
      int c = tid + it * TB;
      int row = c >> 5, cq = c & 31;          // cq = lane: coalesced
      float4 v = *reinterpret_cast<const float4*>(Qb + (size_t)(q0 + row) * HD + cq * 4);
      uint32_t h0, l0, h1, l1;
      splith(v.x * SC, v.y * SC, h0, l0);
      splith(v.z * SC, v.w * SC, h1, l1);
      sts64(adr256(sb + SM_QH, row, cq * 8), h0, h1);
      sts64(adr256(sb + SM_QL, row, cq * 8), l0, l1);
    }
  }

  float m_[2][2], l_[2][2], OA[2][4][4];
  #pragma unroll
  for (int mt = 0; mt < 2; ++mt)
    #pragma unroll
    for (int h2 = 0; h2 < 2; ++h2) { m_[mt][h2] = -1e30f; l_[mt][h2] = 0.f; }
  #pragma unroll
  for (int mt = 0; mt < 2; ++mt)
    #pragma unroll
    for (int nt = 0; nt < 4; ++nt)
      #pragma unroll
      for (int e = 0; e < 4; ++e) OA[mt][nt][e] = 0.f;

  for (int jt = 0; jt < NT; ++jt) {
    const int j0 = jt * BKV;
    __syncthreads();   // prev AV readers done with K/V/P smem

    // ---- K,V -> split halves (coalesced LDG.128, swizzled STS.64) ---------
    #pragma unroll
    for (int it = 0; it < 8; ++it) {
      int c = tid + it * TB;
      int row = c >> 5, cq = c & 31;
      float4 v = *reinterpret_cast<const float4*>(Kb + (size_t)(j0 + row) * HD + cq * 4);
      uint32_t h0, l0, h1, l1;
      splith(v.x, v.y, h0, l0);
      splith(v.z, v.w, h1, l1);
      sts64(adr256(sb + SM_KH, row, cq * 8), h0, h1);
      sts64(adr256(sb + SM_KL, row, cq * 8), l0, l1);
    }
    #pragma unroll
    for (int it = 0; it < 8; ++it) {
      int c = tid + it * TB;
      int row = c >> 5, cq = c & 31;
      float4 v = *reinterpret_cast<const float4*>(Vb + (size_t)(j0 + row) * HD + cq * 4);
      uint32_t h0, l0, h1, l1;
      splith(v.x, v.y, h0, l0);
      splith(v.z, v.w, h1, l1);
      sts64(adr256(sb + SM_VH, row, cq * 8), h0, h1);
      sts64(adr256(sb + SM_VL, row, cq * 8), l0, l1);
    }
    __syncthreads();

    // ---- S = Q K^T: warp rows 32wr+{0,16}, cols 16wc ----------------------
    float acc[2][2][4];
    #pragma unroll
    for (int mt = 0; mt < 2; ++mt)
      #pragma unroll
      for (int nt = 0; nt < 2; ++nt)
        #pragma unroll
        for (int e = 0; e < 4; ++e) acc[mt][nt][e] = 0.f;

    #pragma unroll
    for (int ks = 0; ks < 8; ++ks) {
      int k0 = ks * 16;
      uint32_t ah0[4], ah1[4], al0[4], al1[4], bh[4], bl[4];
      ldsm4(ah0, tadrA(sb + SM_QH, 32 * wr,      k0, lane));
      ldsm4(ah1, tadrA(sb + SM_QH, 32 * wr + 16, k0, lane));
      ldsm4(al0, tadrA(sb + SM_QL, 32 * wr,      k0, lane));
      ldsm4(al1, tadrA(sb + SM_QL, 32 * wr + 16, k0, lane));
      ldsm4(bh,  tadrA(sb + SM_KH, 16 * wc,      k0, lane));
      ldsm4(bl,  tadrA(sb + SM_KL, 16 * wc,      k0, lane));
      mma_(acc[0][0], ah0, bh[0], bh[2]); mma_(acc[0][1], ah0, bh[1], bh[3]);
      mma_(acc[1][0], ah1, bh[0], bh[2]); mma_(acc[1][1], ah1, bh[1], bh[3]);
      mma_(acc[0][0], ah0, bl[0], bl[2]); mma_(acc[0][1], ah0, bl[1], bl[3]);
      mma_(acc[1][0], ah1, bl[0], bl[2]); mma_(acc[1][1], ah1, bl[1], bl[3]);
      mma_(acc[0][0], al0, bh[0], bh[2]); mma_(acc[0][1], al0, bh[1], bh[3]);
      mma_(acc[1][0], al1, bh[0], bh[2]); mma_(acc[1][1], al1, bh[1], bh[3]);
    }

    // ---- softmax: warp-local (mw, sw), one sync ---------------------------
    float mw[2][2];
    #pragma unroll
    for (int mt = 0; mt < 2; ++mt)
      #pragma unroll
      for (int h2 = 0; h2 < 2; ++h2) {
        float v0 = acc[mt][0][2*h2], v1 = acc[mt][0][2*h2+1];
        float v2 = acc[mt][1][2*h2], v3 = acc[mt][1][2*h2+1];
        float mx = fmaxf(fmaxf(v0, v1), fmaxf(v2, v3));
        mx = fmaxf(mx, __shfl_xor_sync(0xffffffffu, mx, 1));
        mx = fmaxf(mx, __shfl_xor_sync(0xffffffffu, mx, 2));
        mw[mt][h2] = mx;
        float s = 0.f;
        #pragma unroll
        for (int nt = 0; nt < 2; ++nt)
          #pragma unroll
          for (int e = 0; e < 2; ++e) {
            float ex = __expf(acc[mt][nt][2*h2+e] - mx);
            acc[mt][nt][2*h2+e] = ex;
            s += ex;
          }
        s += __shfl_xor_sync(0xffffffffu, s, 1);
        s += __shfl_xor_sync(0xffffffffu, s, 2);
        if ((lane & 3) == 0) {
          int row = 32 * wr + 16 * mt + 8 * h2 + (lane >> 2);
          RED[wc * 64 + row] = make_float2(mx, s);
        }
      }
    __syncthreads();

    float corr[2][2], f_[2][2];
    #pragma unroll
    for (int mt = 0; mt < 2; ++mt)
      #pragma unroll
      for (int h2 = 0; h2 < 2; ++h2) {
        int row = 32 * wr + 16 * mt + 8 * h2 + (lane >> 2);
        float2 rw[4];
        #pragma unroll
        for (int w2 = 0; w2 < 4; ++w2) rw[w2] = RED[w2 * 64 + row];
        float mnew = m_[mt][h2];
        #pragma unroll
        for (int w2 = 0; w2 < 4; ++w2) mnew = fmaxf(mnew, rw[w2].x);
        float c_ = __expf(m_[mt][h2] - mnew);
        float ls = l_[mt][h2] * c_;
        #pragma unroll
        for (int w2 = 0; w2 < 4; ++w2) ls += rw[w2].y * __expf(rw[w2].x - mnew);
        corr[mt][h2] = c_;
        f_[mt][h2]   = __expf(mw[mt][h2] - mnew);
        l_[mt][h2] = ls;
        m_[mt][h2] = mnew;
      }

    // ---- dropout + P (hi only) -> smem ------------------------------------
    #pragma unroll
    for (int mt = 0; mt < 2; ++mt)
      #pragma unroll
      for (int h2 = 0; h2 < 2; ++h2) {
        int row = 32 * wr + 16 * mt + 8 * h2 + (lane >> 2);
        float fr = f_[mt][h2];
        unsigned ib = (gbase + (unsigned)row) * (unsigned)NKV
                    + (unsigned)(j0 + 16 * wc + 2 * (lane & 3));
        float e0 = keep_mask(ib)      ? acc[mt][0][2*h2]   * fr : 0.f;
        float e1 = keep_mask(ib + 1u) ? acc[mt][0][2*h2+1] * fr : 0.f;
        float e2 = keep_mask(ib + 8u) ? acc[mt][1][2*h2]   * fr : 0.f;
        float e3 = keep_mask(ib + 9u) ? acc[mt][1][2*h2+1] * fr : 0.f;
        int colB = (16 * wc + 2 * (lane & 3)) * 2;
        sts32(adr128(sb + SM_PH, row, colB),      packh(e0, e1));
        sts32(adr128(sb + SM_PH, row, colB + 16), packh(e2, e3));
      }
    __syncthreads();

    // ---- O = O*corr + P V (V via ldmatrix.trans) --------------------------
    #pragma unroll
    for (int mt = 0; mt < 2; ++mt)
      #pragma unroll
      for (int nt = 0; nt < 4; ++nt)
        #pragma unroll
        for (int e = 0; e < 4; ++e) OA[mt][nt][e] *= corr[mt][e >> 1];

    #pragma unroll
    for (int ks = 0; ks < 4; ++ks) {
      int k0 = ks * 16;
      uint32_t ph0[4], ph1[4], vhA[4], vhB[4], vlA[4], vlB[4];
      ldsm4(ph0,  tadrP(sb + SM_PH, 32 * wr,      k0, lane));
      ldsm4(ph1,  tadrP(sb + SM_PH, 32 * wr + 16, k0, lane));
      ldsm4t(vhA, tadrVT(sb + SM_VH, 32 * wc,      k0, lane));
      ldsm4t(vhB, tadrVT(sb + SM_VH, 32 * wc + 16, k0, lane));
      ldsm4t(vlA, tadrVT(sb + SM_VL, 32 * wc,      k0, lane));
      ldsm4t(vlB, tadrVT(sb + SM_VL, 32 * wc + 16, k0, lane));
      mma_(OA[0][0], ph0, vhA[0], vhA[2]); mma_(OA[0][1], ph0, vhA[1], vhA[3]);
      mma_(OA[0][2], ph0, vhB[0], vhB[2]); mma_(OA[0][3], ph0, vhB[1], vhB[3]);
      mma_(OA[1][0], ph1, vhA[0], vhA[2]); mma_(OA[1][1], ph1, vhA[1], vhA[3]);
      mma_(OA[1][2], ph1, vhB[0], vhB[2]); mma_(OA[1][3], ph1, vhB[1], vhB[3]);
      mma_(OA[0][0], ph0, vlA[0], vlA[2]); mma_(OA[0][1], ph0, vlA[1], vlA[3]);
      mma_(OA[0][2], ph0, vlB[0], vlB[2]); mma_(OA[0][3], ph0, vlB[1], vlB[3]);
      mma_(OA[1][0], ph1, vlA[0], vlA[2]); mma_(OA[1][1], ph1, vlA[1], vlA[3]);
      mma_(OA[1][2], ph1, vlB[0], vlB[2]); mma_(OA[1][3], ph1, vlB[1], vlB[3]);
    }
  }

  // ---- epilogue ------------------------------------------------------------
  #pragma unroll
  for (int mt = 0; mt < 2; ++mt) {
    float inv0 = 1.0f / (l_[mt][0] * 0.9f);
    float inv1 = 1.0f / (l_[mt][1] * 0.9f);
    #pragma unroll
    for (int nt = 0; nt < 4; ++nt) {
      int col = 32 * wc + 8 * nt + 2 * (lane & 3);
      #pragma unroll
      for (int h2 = 0; h2 < 2; ++h2) {
        int row = 32 * wr + 16 * mt + 8 * h2 + (lane >> 2);
        float inv = h2 ? inv1 : inv0;
        float2 o;
        o.x = OA[mt][nt][2*h2]   * inv;
        o.y = OA[mt][nt][2*h2+1] * inv;
        *reinterpret_cast<float2*>(Og + (size_t)(gbase + row) * HD + col) = o;
      }
    }
  }
}

extern "C" void kernel_launch(void* const* d_in, const int* in_sizes, int n_in,
                              void* d_out, int out_size) {
  const float* Q = (const float*)d_in[0];
  const float* K = (const float*)d_in[1];
  const float* V = (const float*)d_in[2];
  float* O = (float*)d_out;
  (void)in_sizes; (void)n_in; (void)out_size;
  cudaFuncSetAttribute(Model_56358560858161_kernel,
                       cudaFuncAttributeMaxDynamicSharedMemorySize, (int)SM_TOT);
  Model_56358560858161_kernel<<<256, TB, SM_TOT>>>(Q, K, V, O);
}